// round 1
// baseline (speedup 1.0000x reference)
#include <cuda_runtime.h>
#include <math.h>

#define B_ 2
#define T_ 2048
#define C_ 2048
#define H_ 16
#define D_ 128
#define M_ (B_*T_)   // 4096 rows

// ---------------- scratch (device globals; no allocation allowed) -------------
__device__ float g_q [M_*C_];
__device__ float g_k [M_*C_];
__device__ float g_v [M_*C_];
__device__ float g_qt[M_*C_];   // [b][h][d][t]
__device__ float g_kt[M_*C_];   // [b][h][d][t]
__device__ float g_y [M_*C_];   // attention output [b][t][h*D+d]
__device__ float g_gate[M_*H_];

// ---------------- gate = 3*sigmoid(x[:, :12] @ Wg^T) --------------------------
__global__ void gate_kernel(const float* __restrict__ x, const float* __restrict__ Wg,
                            float* __restrict__ gate) {
    int idx = blockIdx.x * blockDim.x + threadIdx.x;
    if (idx >= M_ * H_) return;
    int m = idx >> 4, h = idx & 15;
    float s = 0.f;
#pragma unroll
    for (int j = 0; j < 12; j++) s += x[(size_t)m * C_ + j] * Wg[h * 12 + j];
    gate[idx] = 3.f / (1.f + __expf(-s));
}

// ---------------- SGEMM: C[m,n] = sum_k A[m,k] * W[n,k]  (M=4096,N=2048,K=2048)
// BM=BN=128, BK=8, 256 threads, 8x8 fragments.
// EPI==1: v epilogue (C += gate[m,h]*ve[m,n])
template<int EPI>
__global__ __launch_bounds__(256) void sgemm_k(const float* __restrict__ A,
                                               const float* __restrict__ W,
                                               float* __restrict__ Cout,
                                               const float* __restrict__ ve,
                                               const float* __restrict__ gate) {
    __shared__ float As[8][128];
    __shared__ float Bs[8][128];
    const int tid = threadIdx.x;
    const int lr = tid >> 1;           // 0..127
    const int lc = (tid & 1) << 2;     // 0 or 4
    const int tr = tid >> 4;           // 0..15
    const int tc = tid & 15;           // 0..15

    const float* Ap = A + (size_t)(blockIdx.y * 128 + lr) * C_ + lc;
    const float* Wp = W + (size_t)(blockIdx.x * 128 + lr) * C_ + lc;

    float acc[8][8];
#pragma unroll
    for (int i = 0; i < 8; i++)
#pragma unroll
        for (int j = 0; j < 8; j++) acc[i][j] = 0.f;

    for (int k0 = 0; k0 < C_; k0 += 8) {
        float4 av = *(const float4*)(Ap + k0);
        float4 bv = *(const float4*)(Wp + k0);
        As[lc + 0][lr] = av.x; As[lc + 1][lr] = av.y;
        As[lc + 2][lr] = av.z; As[lc + 3][lr] = av.w;
        Bs[lc + 0][lr] = bv.x; Bs[lc + 1][lr] = bv.y;
        Bs[lc + 2][lr] = bv.z; Bs[lc + 3][lr] = bv.w;
        __syncthreads();
#pragma unroll
        for (int kk = 0; kk < 8; kk++) {
            float a[8], b[8];
            *(float4*)&a[0] = *(const float4*)&As[kk][tr * 8];
            *(float4*)&a[4] = *(const float4*)&As[kk][tr * 8 + 4];
            *(float4*)&b[0] = *(const float4*)&Bs[kk][tc * 8];
            *(float4*)&b[4] = *(const float4*)&Bs[kk][tc * 8 + 4];
#pragma unroll
            for (int i = 0; i < 8; i++)
#pragma unroll
                for (int j = 0; j < 8; j++) acc[i][j] += a[i] * b[j];
        }
        __syncthreads();
    }

#pragma unroll
    for (int i = 0; i < 8; i++) {
        int m = blockIdx.y * 128 + tr * 8 + i;
#pragma unroll
        for (int j = 0; j < 8; j++) {
            int n = blockIdx.x * 128 + tc * 8 + j;
            float val = acc[i][j];
            if (EPI == 1)
                val += gate[m * H_ + (n >> 7)] * ve[(size_t)m * C_ + n];
            Cout[(size_t)m * C_ + n] = val;
        }
    }
}

// ---------------- RoPE + RMSnorm (+1.2 scale), writes [b][h][d][t] transposed --
__global__ void rope_kernel(const float* __restrict__ src, float* __restrict__ dst,
                            const float* __restrict__ cosp, const float* __restrict__ sinp) {
    int warp = blockIdx.x * (blockDim.x >> 5) + (threadIdx.x >> 5);
    int lane = threadIdx.x & 31;
    int m = warp >> 4, h = warp & 15;       // warp per (row, head)
    int b = m >> 11, t = m & 2047;
    const float* row = src + (size_t)m * C_ + h * D_;
    float y1[2], y2[2];
    float ss = 0.f;
#pragma unroll
    for (int i = 0; i < 2; i++) {
        int d1 = lane + i * 32;             // 0..63
        float x1 = row[d1], x2 = row[d1 + 64];
        float c = cosp[t * 64 + d1], s = sinp[t * 64 + d1];
        y1[i] = x1 * c + x2 * s;
        y2[i] = x2 * c - x1 * s;
        ss += y1[i] * y1[i] + y2[i] * y2[i];
    }
#pragma unroll
    for (int off = 16; off; off >>= 1) ss += __shfl_xor_sync(0xffffffffu, ss, off);
    float r = rsqrtf(ss * (1.f / 128.f) + 1e-6f) * 1.2f;
    float* drow = dst + (size_t)(b * H_ + h) * D_ * T_;
#pragma unroll
    for (int i = 0; i < 2; i++) {
        int d1 = lane + i * 32;
        drow[(size_t)d1 * T_ + t] = y1[i] * r;
        drow[(size_t)(d1 + 64) * T_ + t] = y2[i] * r;
    }
}

// ---------------- flash attention, fp32, sliding window ----------------------
// block: (q-tile 64) x (head) x (batch). 256 threads.
// smem: Qs[128][64], Ks[128][64], Vs[64][128], Ps[64][65]
__global__ __launch_bounds__(256) void attn_kernel(const float* __restrict__ qt,
                                                   const float* __restrict__ kt,
                                                   const float* __restrict__ v,
                                                   float* __restrict__ y,
                                                   const int* __restrict__ winp) {
    extern __shared__ float sm[];
    float* Qs = sm;                 // 8192
    float* Ks = sm + 8192;          // 8192
    float* Vs = sm + 16384;         // 8192
    float* Ps = sm + 24576;         // 64*65 = 4160

    const int tid = threadIdx.x;
    const int t0 = blockIdx.x * 64;
    const int h = blockIdx.y, b = blockIdx.z;
    int win = *winp;
    if (win <= 0 || win >= T_) win = T_;

    const int tr = tid >> 4, tc = tid & 15;
    const int dO = tc * 8;

    const float* qbase = qt + (size_t)(b * H_ + h) * D_ * T_;
    const float* kbase = kt + (size_t)(b * H_ + h) * D_ * T_;
    const float* vbase = v + (size_t)(b * T_) * C_ + h * D_;

    // load Q tile transposed layout Qs[d][m]
#pragma unroll
    for (int it = 0; it < 8; it++) {
        int f = tid + it * 256;            // float4 index over 128x64
        int d = f >> 4, n4 = f & 15;
        *(float4*)&Qs[d * 64 + n4 * 4] = *(const float4*)&qbase[(size_t)d * T_ + t0 + n4 * 4];
    }

    float o[4][8];
    float row_m[4], row_l[4];
#pragma unroll
    for (int i = 0; i < 4; i++) {
        row_m[i] = -1e30f; row_l[i] = 0.f;
#pragma unroll
        for (int j = 0; j < 8; j++) o[i][j] = 0.f;
    }

    int start = t0 - win;
    if (start < 0) start = 0;
    start &= ~63;

    for (int k0 = start; k0 <= t0; k0 += 64) {
        // load K tile Ks[d][n] and V tile Vs[k][d]
#pragma unroll
        for (int it = 0; it < 8; it++) {
            int f = tid + it * 256;
            int d = f >> 4, n4 = f & 15;
            *(float4*)&Ks[d * 64 + n4 * 4] = *(const float4*)&kbase[(size_t)d * T_ + k0 + n4 * 4];
        }
#pragma unroll
        for (int it = 0; it < 8; it++) {
            int f = tid + it * 256;
            int kk = f >> 5, d4 = f & 31;
            *(float4*)&Vs[kk * 128 + d4 * 4] = *(const float4*)&vbase[(size_t)(k0 + kk) * C_ + d4 * 4];
        }
        __syncthreads();

        // S = Q K^T fragment (4x4 per thread)
        float s[4][4];
#pragma unroll
        for (int i = 0; i < 4; i++)
#pragma unroll
            for (int j = 0; j < 4; j++) s[i][j] = 0.f;
#pragma unroll 8
        for (int d = 0; d < 128; d++) {
            float qa[4], ka[4];
            *(float4*)qa = *(const float4*)&Qs[d * 64 + tr * 4];
            *(float4*)ka = *(const float4*)&Ks[d * 64 + tc * 4];
#pragma unroll
            for (int i = 0; i < 4; i++)
#pragma unroll
                for (int j = 0; j < 4; j++) s[i][j] += qa[i] * ka[j];
        }

        const float sc = 0.08838834764831845f;  // 1/sqrt(128)
#pragma unroll
        for (int i = 0; i < 4; i++) {
            int qi = t0 + tr * 4 + i;
            float sv[4];
            float mx = -1e30f;
#pragma unroll
            for (int j = 0; j < 4; j++) {
                int kj = k0 + tc * 4 + j;
                bool ok = (kj <= qi) && (qi - kj <= win);
                sv[j] = ok ? s[i][j] * sc : -1e30f;
                mx = fmaxf(mx, sv[j]);
            }
            mx = fmaxf(mx, __shfl_xor_sync(0xffffffffu, mx, 8));
            mx = fmaxf(mx, __shfl_xor_sync(0xffffffffu, mx, 4));
            mx = fmaxf(mx, __shfl_xor_sync(0xffffffffu, mx, 2));
            mx = fmaxf(mx, __shfl_xor_sync(0xffffffffu, mx, 1));
            float mnew = fmaxf(row_m[i], mx);
            float corr = __expf(row_m[i] - mnew);
            float lsum = 0.f;
#pragma unroll
            for (int j = 0; j < 4; j++) {
                float p = (sv[j] < -1e29f) ? 0.f : __expf(sv[j] - mnew);
                Ps[(tr * 4 + i) * 65 + tc * 4 + j] = p;
                lsum += p;
            }
            lsum += __shfl_xor_sync(0xffffffffu, lsum, 8);
            lsum += __shfl_xor_sync(0xffffffffu, lsum, 4);
            lsum += __shfl_xor_sync(0xffffffffu, lsum, 2);
            lsum += __shfl_xor_sync(0xffffffffu, lsum, 1);
            row_l[i] = row_l[i] * corr + lsum;
            row_m[i] = mnew;
#pragma unroll
            for (int j = 0; j < 8; j++) o[i][j] *= corr;
        }
        __syncthreads();

        // O += P V
#pragma unroll 4
        for (int kk = 0; kk < 64; kk++) {
            float vv[8];
            *(float4*)&vv[0] = *(const float4*)&Vs[kk * 128 + dO];
            *(float4*)&vv[4] = *(const float4*)&Vs[kk * 128 + dO + 4];
#pragma unroll
            for (int i = 0; i < 4; i++) {
                float p = Ps[(tr * 4 + i) * 65 + kk];
#pragma unroll
                for (int j = 0; j < 8; j++) o[i][j] += p * vv[j];
            }
        }
        __syncthreads();
    }

    // write normalized output: y[b][t][h*D + d]
#pragma unroll
    for (int i = 0; i < 4; i++) {
        int m = t0 + tr * 4 + i;
        float inv = 1.f / row_l[i];
        float* dst = y + (size_t)(b * T_ + m) * C_ + h * D_ + dO;
        float4 w0 = make_float4(o[i][0] * inv, o[i][1] * inv, o[i][2] * inv, o[i][3] * inv);
        float4 w1 = make_float4(o[i][4] * inv, o[i][5] * inv, o[i][6] * inv, o[i][7] * inv);
        *(float4*)&dst[0] = w0;
        *(float4*)&dst[4] = w1;
    }
}

// ---------------- launch ------------------------------------------------------
extern "C" void kernel_launch(void* const* d_in, const int* in_sizes, int n_in,
                              void* d_out, int out_size) {
    const float* x     = (const float*)d_in[0];
    const float* ve    = (const float*)d_in[1];
    const float* Wq    = (const float*)d_in[2];
    const float* Wk    = (const float*)d_in[3];
    const float* Wv    = (const float*)d_in[4];
    const float* Wproj = (const float*)d_in[5];
    const float* Wg    = (const float*)d_in[6];
    const float* cosp  = (const float*)d_in[7];
    const float* sinp  = (const float*)d_in[8];
    const int*   winp  = (const int*)d_in[9];
    float* out = (float*)d_out;

    void *pq, *pk, *pv, *pqt, *pkt, *py, *pg;
    cudaGetSymbolAddress(&pq,  g_q);
    cudaGetSymbolAddress(&pk,  g_k);
    cudaGetSymbolAddress(&pv,  g_v);
    cudaGetSymbolAddress(&pqt, g_qt);
    cudaGetSymbolAddress(&pkt, g_kt);
    cudaGetSymbolAddress(&py,  g_y);
    cudaGetSymbolAddress(&pg,  g_gate);

    // 1) gate
    gate_kernel<<<(M_ * H_ + 255) / 256, 256>>>(x, Wg, (float*)pg);

    // 2) q, k, v projections
    dim3 ggrid(16, 32);
    sgemm_k<0><<<ggrid, 256>>>(x, Wq, (float*)pq, nullptr, nullptr);
    sgemm_k<0><<<ggrid, 256>>>(x, Wk, (float*)pk, nullptr, nullptr);
    sgemm_k<1><<<ggrid, 256>>>(x, Wv, (float*)pv, ve, (const float*)pg);

    // 3) rope + rmsnorm (writes transposed [b][h][d][t])
    rope_kernel<<<8192, 256>>>((const float*)pq, (float*)pqt, cosp, sinp);
    rope_kernel<<<8192, 256>>>((const float*)pk, (float*)pkt, cosp, sinp);

    // 4) attention
    size_t smem = (size_t)(8192 * 3 + 64 * 65) * sizeof(float);  // 114,944 B
    cudaFuncSetAttribute(attn_kernel, cudaFuncAttributeMaxDynamicSharedMemorySize, (int)smem);
    attn_kernel<<<dim3(32, H_, B_), 256, smem>>>((const float*)pqt, (const float*)pkt,
                                                 (const float*)pv, (float*)py, winp);

    // 5) output projection
    sgemm_k<0><<<ggrid, 256>>>((const float*)py, Wproj, out, nullptr, nullptr);
}

// round 3
// speedup vs baseline: 1.7702x; 1.7702x over previous
#include <cuda_runtime.h>
#include <cuda_bf16.h>
#include <math.h>
#include <stdint.h>

#define B_ 2
#define T_ 2048
#define C_ 2048
#define H_ 16
#define D_ 128
#define M_ (B_*T_)   // 4096 rows

// ---------------- scratch (device globals; no allocation allowed) -------------
__device__ float g_q [M_*C_];
__device__ float g_k [M_*C_];
__device__ float g_v [M_*C_];
__device__ float g_qt[M_*C_];   // [b][h][d][t]
__device__ float g_kt[M_*C_];   // [b][h][d][t]
__device__ float g_y [M_*C_];   // attention output [b][t][h*D+d]
__device__ float g_gate[M_*H_];

// bf16 hi/lo split buffers
__device__ __nv_bfloat16 g_xh[M_*C_],  g_xl[M_*C_];
__device__ __nv_bfloat16 g_yh[M_*C_],  g_yl[M_*C_];
__device__ __nv_bfloat16 g_wqh[C_*C_], g_wql[C_*C_];
__device__ __nv_bfloat16 g_wkh[C_*C_], g_wkl[C_*C_];
__device__ __nv_bfloat16 g_wvh[C_*C_], g_wvl[C_*C_];
__device__ __nv_bfloat16 g_wph[C_*C_], g_wpl[C_*C_];

// ================= PTX helpers =================
__device__ __forceinline__ uint32_t smem_u32(const void* p) {
    uint32_t a;
    asm("{ .reg .u64 t; cvta.to.shared.u64 t, %1; cvt.u32.u64 %0, t; }" : "=r"(a) : "l"(p));
    return a;
}
__device__ __forceinline__ void cpasync16(uint32_t saddr, const void* gaddr) {
    asm volatile("cp.async.cg.shared.global [%0], [%1], 16;" :: "r"(saddr), "l"(gaddr) : "memory");
}
__device__ __forceinline__ void ldsm4(uint32_t addr, uint32_t* r) {
    asm volatile("ldmatrix.sync.aligned.m8n8.x4.shared.b16 {%0,%1,%2,%3}, [%4];"
                 : "=r"(r[0]), "=r"(r[1]), "=r"(r[2]), "=r"(r[3]) : "r"(addr));
}
#define MMA_BF16(Cf, Af, B0, B1)                                              \
    asm volatile("mma.sync.aligned.m16n8k16.row.col.f32.bf16.bf16.f32 "        \
        "{%0,%1,%2,%3},{%4,%5,%6,%7},{%8,%9},{%0,%1,%2,%3};"                   \
        : "+f"((Cf)[0]), "+f"((Cf)[1]), "+f"((Cf)[2]), "+f"((Cf)[3])           \
        : "r"((Af)[0]), "r"((Af)[1]), "r"((Af)[2]), "r"((Af)[3]),              \
          "r"(B0), "r"(B1))

// ---------------- fp32 -> bf16 hi/lo split ------------------------------------
__global__ void split_kernel(const float* __restrict__ src,
                             __nv_bfloat16* __restrict__ hi,
                             __nv_bfloat16* __restrict__ lo, int n) {
    int i = (blockIdx.x * blockDim.x + threadIdx.x) * 4;
    if (i >= n) return;
    float4 v = *(const float4*)(src + i);
    __nv_bfloat16 h0 = __float2bfloat16(v.x), h1 = __float2bfloat16(v.y);
    __nv_bfloat16 h2 = __float2bfloat16(v.z), h3 = __float2bfloat16(v.w);
    __nv_bfloat16 l0 = __float2bfloat16(v.x - __bfloat162float(h0));
    __nv_bfloat16 l1 = __float2bfloat16(v.y - __bfloat162float(h1));
    __nv_bfloat16 l2 = __float2bfloat16(v.z - __bfloat162float(h2));
    __nv_bfloat16 l3 = __float2bfloat16(v.w - __bfloat162float(h3));
    ((__nv_bfloat162*)(hi + i))[0] = __nv_bfloat162(h0, h1);
    ((__nv_bfloat162*)(hi + i))[1] = __nv_bfloat162(h2, h3);
    ((__nv_bfloat162*)(lo + i))[0] = __nv_bfloat162(l0, l1);
    ((__nv_bfloat162*)(lo + i))[1] = __nv_bfloat162(l2, l3);
}

// ---------------- gate = 3*sigmoid(x[:, :12] @ Wg^T) --------------------------
__global__ void gate_kernel(const float* __restrict__ x, const float* __restrict__ Wg,
                            float* __restrict__ gate) {
    int idx = blockIdx.x * blockDim.x + threadIdx.x;
    if (idx >= M_ * H_) return;
    int m = idx >> 4, h = idx & 15;
    float s = 0.f;
#pragma unroll
    for (int j = 0; j < 12; j++) s += x[(size_t)m * C_ + j] * Wg[h * 12 + j];
    gate[idx] = 3.f / (1.f + __expf(-s));
}

// ---------------- mma.sync bf16 split GEMM ------------------------------------
// C[m,n] = sum_k A[m,k]*B[n,k], fp32 via bf16 hi/lo split (AhBh + AhBl + AlBh).
// BM=BN=128, BK=32, 3-stage cp.async pipeline, 8 warps (4m x 2n), warp tile 32x64.
// SMEM rows padded to 40 bf16 (80 B) -> conflict-free ldmatrix & cp.async.
#define RS_E 40
#define RS_B 80
#define ARR_B (128 * RS_B)          // 10240 bytes per array
#define STG_B (4 * ARR_B)           // 40960 per stage (Ah|Al|Bh|Bl)
#define NSTAGE 3
#define NCHUNK 64                   // 2048 / 32
#define GEMM_SMEM (NSTAGE * STG_B)  // 122880

template<int EPI>
__global__ __launch_bounds__(256, 1) void gemm_mma(
    const __nv_bfloat16* __restrict__ Ah, const __nv_bfloat16* __restrict__ Al,
    const __nv_bfloat16* __restrict__ Bh, const __nv_bfloat16* __restrict__ Bl,
    float* __restrict__ Cout,
    const float* __restrict__ ve, const float* __restrict__ gate) {
    extern __shared__ char smc[];
    const uint32_t sb = smem_u32(smc);
    const int tid = threadIdx.x;
    const int wid = tid >> 5, lane = tid & 31;
    const int warp_m = wid & 3, warp_n = wid >> 2;
    const int arow0 = blockIdx.y * 128, brow0 = blockIdx.x * 128;

    auto load_chunk = [&](int stage, int chunk) {
        const int k0 = chunk * 32;
        uint32_t stg = sb + stage * STG_B;
#pragma unroll
        for (int j = 0; j < 8; j++) {
            int u = tid + j * 256;           // 0..2047
            int arr = u >> 9;
            int rc = u & 511;
            int r = rc >> 2, c = rc & 3;
            uint32_t sa = stg + arr * ARR_B + r * RS_B + c * 16;
            const __nv_bfloat16* src;
            size_t off;
            if (arr < 2) {
                src = (arr == 0) ? Ah : Al;
                off = (size_t)(arow0 + r) * C_ + k0 + c * 8;
            } else {
                src = (arr == 2) ? Bh : Bl;
                off = (size_t)(brow0 + r) * C_ + k0 + c * 8;
            }
            cpasync16(sa, src + off);
        }
        asm volatile("cp.async.commit_group;" ::: "memory");
    };

    float acc[2][8][4];
#pragma unroll
    for (int mi = 0; mi < 2; mi++)
#pragma unroll
        for (int nf = 0; nf < 8; nf++)
#pragma unroll
            for (int q = 0; q < 4; q++) acc[mi][nf][q] = 0.f;

    load_chunk(0, 0);
    load_chunk(1, 1);

    const uint32_t a_lane_off = (uint32_t)((warp_m * 32 + (lane & 15)) * RS_B + (lane >> 4) * 16);
    const uint32_t b_lane_off = (uint32_t)((warp_n * 64 + (lane & 15)) * RS_B + (lane >> 4) * 16);

    for (int i = 0; i < NCHUNK; i++) {
        if (i < NCHUNK - 1) asm volatile("cp.async.wait_group 1;" ::: "memory");
        else                asm volatile("cp.async.wait_group 0;" ::: "memory");
        __syncthreads();
        if (i + 2 < NCHUNK) load_chunk((i + 2) % NSTAGE, i + 2);

        uint32_t stg = sb + (i % NSTAGE) * STG_B;
#pragma unroll
        for (int ks = 0; ks < 2; ks++) {
            uint32_t a_h[2][4], a_l[2][4];
            uint32_t b_h[8][2], b_l[8][2];
            uint32_t koff = ks * 32;
#pragma unroll
            for (int mi = 0; mi < 2; mi++) {
                ldsm4(stg + 0 * ARR_B + a_lane_off + mi * 16 * RS_B + koff, a_h[mi]);
                ldsm4(stg + 1 * ARR_B + a_lane_off + mi * 16 * RS_B + koff, a_l[mi]);
            }
#pragma unroll
            for (int nf4 = 0; nf4 < 4; nf4++) {
                uint32_t t[4];
                ldsm4(stg + 2 * ARR_B + b_lane_off + nf4 * 16 * RS_B + koff, t);
                b_h[nf4 * 2][0] = t[0]; b_h[nf4 * 2][1] = t[2];
                b_h[nf4 * 2 + 1][0] = t[1]; b_h[nf4 * 2 + 1][1] = t[3];
                ldsm4(stg + 3 * ARR_B + b_lane_off + nf4 * 16 * RS_B + koff, t);
                b_l[nf4 * 2][0] = t[0]; b_l[nf4 * 2][1] = t[2];
                b_l[nf4 * 2 + 1][0] = t[1]; b_l[nf4 * 2 + 1][1] = t[3];
            }
#pragma unroll
            for (int mi = 0; mi < 2; mi++)
#pragma unroll
                for (int nf = 0; nf < 8; nf++) {
                    MMA_BF16(acc[mi][nf], a_h[mi], b_h[nf][0], b_h[nf][1]);
                    MMA_BF16(acc[mi][nf], a_h[mi], b_l[nf][0], b_l[nf][1]);
                    MMA_BF16(acc[mi][nf], a_l[mi], b_h[nf][0], b_h[nf][1]);
                }
        }
    }

    // epilogue: direct register -> global (float2 stores)
    const int r0w = arow0 + warp_m * 32 + (lane >> 2);
    const int c0w = brow0 + warp_n * 64 + (lane & 3) * 2;
#pragma unroll
    for (int mi = 0; mi < 2; mi++) {
#pragma unroll
        for (int nf = 0; nf < 8; nf++) {
            int n = c0w + nf * 8;
            int m0 = r0w + mi * 16;
            int m1 = m0 + 8;
            float v0 = acc[mi][nf][0], v1 = acc[mi][nf][1];
            float v2 = acc[mi][nf][2], v3 = acc[mi][nf][3];
            if (EPI) {
                float g0 = gate[m0 * H_ + (n >> 7)];
                float g1 = gate[m1 * H_ + (n >> 7)];
                const float* ve0 = ve + (size_t)m0 * C_ + n;
                const float* ve1 = ve + (size_t)m1 * C_ + n;
                v0 += g0 * ve0[0]; v1 += g0 * ve0[1];
                v2 += g1 * ve1[0]; v3 += g1 * ve1[1];
            }
            *(float2*)(Cout + (size_t)m0 * C_ + n) = make_float2(v0, v1);
            *(float2*)(Cout + (size_t)m1 * C_ + n) = make_float2(v2, v3);
        }
    }
}

// ---------------- RoPE + RMSnorm (+1.2 scale), writes [b][h][d][t] transposed --
__global__ void rope_kernel(const float* __restrict__ src, float* __restrict__ dst,
                            const float* __restrict__ cosp, const float* __restrict__ sinp) {
    int warp = blockIdx.x * (blockDim.x >> 5) + (threadIdx.x >> 5);
    int lane = threadIdx.x & 31;
    int m = warp >> 4, h = warp & 15;
    int b = m >> 11, t = m & 2047;
    const float* row = src + (size_t)m * C_ + h * D_;
    float y1[2], y2[2];
    float ss = 0.f;
#pragma unroll
    for (int i = 0; i < 2; i++) {
        int d1 = lane + i * 32;
        float x1 = row[d1], x2 = row[d1 + 64];
        float c = cosp[t * 64 + d1], s = sinp[t * 64 + d1];
        y1[i] = x1 * c + x2 * s;
        y2[i] = x2 * c - x1 * s;
        ss += y1[i] * y1[i] + y2[i] * y2[i];
    }
#pragma unroll
    for (int off = 16; off; off >>= 1) ss += __shfl_xor_sync(0xffffffffu, ss, off);
    float r = rsqrtf(ss * (1.f / 128.f) + 1e-6f) * 1.2f;
    float* drow = dst + (size_t)(b * H_ + h) * D_ * T_;
#pragma unroll
    for (int i = 0; i < 2; i++) {
        int d1 = lane + i * 32;
        drow[(size_t)d1 * T_ + t] = y1[i] * r;
        drow[(size_t)(d1 + 64) * T_ + t] = y2[i] * r;
    }
}

// ---------------- flash attention, fp32, sliding window ----------------------
__global__ __launch_bounds__(256) void attn_kernel(const float* __restrict__ qt,
                                                   const float* __restrict__ kt,
                                                   const float* __restrict__ v,
                                                   float* __restrict__ y,
                                                   const int* __restrict__ winp) {
    extern __shared__ float sm[];
    float* Qs = sm;                 // 8192
    float* Ks = sm + 8192;          // 8192
    float* Vs = sm + 16384;         // 8192
    float* Ps = sm + 24576;         // 64*65

    const int tid = threadIdx.x;
    const int t0 = blockIdx.x * 64;
    const int h = blockIdx.y, b = blockIdx.z;
    int win = *winp;
    if (win <= 0 || win >= T_) win = T_;

    const int tr = tid >> 4, tc = tid & 15;
    const int dO = tc * 8;

    const float* qbase = qt + (size_t)(b * H_ + h) * D_ * T_;
    const float* kbase = kt + (size_t)(b * H_ + h) * D_ * T_;
    const float* vbase = v + (size_t)(b * T_) * C_ + h * D_;

#pragma unroll
    for (int it = 0; it < 8; it++) {
        int f = tid + it * 256;
        int d = f >> 4, n4 = f & 15;
        *(float4*)&Qs[d * 64 + n4 * 4] = *(const float4*)&qbase[(size_t)d * T_ + t0 + n4 * 4];
    }

    float o[4][8];
    float row_m[4], row_l[4];
#pragma unroll
    for (int i = 0; i < 4; i++) {
        row_m[i] = -1e30f; row_l[i] = 0.f;
#pragma unroll
        for (int j = 0; j < 8; j++) o[i][j] = 0.f;
    }

    int start = t0 - win;
    if (start < 0) start = 0;
    start &= ~63;

    for (int k0 = start; k0 <= t0; k0 += 64) {
#pragma unroll
        for (int it = 0; it < 8; it++) {
            int f = tid + it * 256;
            int d = f >> 4, n4 = f & 15;
            *(float4*)&Ks[d * 64 + n4 * 4] = *(const float4*)&kbase[(size_t)d * T_ + k0 + n4 * 4];
        }
#pragma unroll
        for (int it = 0; it < 8; it++) {
            int f = tid + it * 256;
            int kk = f >> 5, d4 = f & 31;
            *(float4*)&Vs[kk * 128 + d4 * 4] = *(const float4*)&vbase[(size_t)(k0 + kk) * C_ + d4 * 4];
        }
        __syncthreads();

        float s[4][4];
#pragma unroll
        for (int i = 0; i < 4; i++)
#pragma unroll
            for (int j = 0; j < 4; j++) s[i][j] = 0.f;
#pragma unroll 8
        for (int d = 0; d < 128; d++) {
            float qa[4], ka[4];
            *(float4*)qa = *(const float4*)&Qs[d * 64 + tr * 4];
            *(float4*)ka = *(const float4*)&Ks[d * 64 + tc * 4];
#pragma unroll
            for (int i = 0; i < 4; i++)
#pragma unroll
                for (int j = 0; j < 4; j++) s[i][j] += qa[i] * ka[j];
        }

        const float sc = 0.08838834764831845f;
#pragma unroll
        for (int i = 0; i < 4; i++) {
            int qi = t0 + tr * 4 + i;
            float sv[4];
            float mx = -1e30f;
#pragma unroll
            for (int j = 0; j < 4; j++) {
                int kj = k0 + tc * 4 + j;
                bool ok = (kj <= qi) && (qi - kj <= win);
                sv[j] = ok ? s[i][j] * sc : -1e30f;
                mx = fmaxf(mx, sv[j]);
            }
            mx = fmaxf(mx, __shfl_xor_sync(0xffffffffu, mx, 8));
            mx = fmaxf(mx, __shfl_xor_sync(0xffffffffu, mx, 4));
            mx = fmaxf(mx, __shfl_xor_sync(0xffffffffu, mx, 2));
            mx = fmaxf(mx, __shfl_xor_sync(0xffffffffu, mx, 1));
            float mnew = fmaxf(row_m[i], mx);
            float corr = __expf(row_m[i] - mnew);
            float lsum = 0.f;
#pragma unroll
            for (int j = 0; j < 4; j++) {
                float p = (sv[j] < -1e29f) ? 0.f : __expf(sv[j] - mnew);
                Ps[(tr * 4 + i) * 65 + tc * 4 + j] = p;
                lsum += p;
            }
            lsum += __shfl_xor_sync(0xffffffffu, lsum, 8);
            lsum += __shfl_xor_sync(0xffffffffu, lsum, 4);
            lsum += __shfl_xor_sync(0xffffffffu, lsum, 2);
            lsum += __shfl_xor_sync(0xffffffffu, lsum, 1);
            row_l[i] = row_l[i] * corr + lsum;
            row_m[i] = mnew;
#pragma unroll
            for (int j = 0; j < 8; j++) o[i][j] *= corr;
        }
        __syncthreads();

#pragma unroll 4
        for (int kk = 0; kk < 64; kk++) {
            float vv[8];
            *(float4*)&vv[0] = *(const float4*)&Vs[kk * 128 + dO];
            *(float4*)&vv[4] = *(const float4*)&Vs[kk * 128 + dO + 4];
#pragma unroll
            for (int i = 0; i < 4; i++) {
                float p = Ps[(tr * 4 + i) * 65 + kk];
#pragma unroll
                for (int j = 0; j < 8; j++) o[i][j] += p * vv[j];
            }
        }
        __syncthreads();
    }

#pragma unroll
    for (int i = 0; i < 4; i++) {
        int m = t0 + tr * 4 + i;
        float inv = 1.f / row_l[i];
        float* dst = y + (size_t)(b * T_ + m) * C_ + h * D_ + dO;
        float4 w0 = make_float4(o[i][0] * inv, o[i][1] * inv, o[i][2] * inv, o[i][3] * inv);
        float4 w1 = make_float4(o[i][4] * inv, o[i][5] * inv, o[i][6] * inv, o[i][7] * inv);
        *(float4*)&dst[0] = w0;
        *(float4*)&dst[4] = w1;
    }
}

// ---------------- launch ------------------------------------------------------
extern "C" void kernel_launch(void* const* d_in, const int* in_sizes, int n_in,
                              void* d_out, int out_size) {
    const float* x     = (const float*)d_in[0];
    const float* ve    = (const float*)d_in[1];
    const float* Wq    = (const float*)d_in[2];
    const float* Wk    = (const float*)d_in[3];
    const float* Wv    = (const float*)d_in[4];
    const float* Wproj = (const float*)d_in[5];
    const float* Wg    = (const float*)d_in[6];
    const float* cosp  = (const float*)d_in[7];
    const float* sinp  = (const float*)d_in[8];
    const int*   winp  = (const int*)d_in[9];
    float* out = (float*)d_out;

    void *pq, *pk, *pv, *pqt, *pkt, *py, *pg;
    void *pxh, *pxl, *pyh, *pyl;
    void *pwqh, *pwql, *pwkh, *pwkl, *pwvh, *pwvl, *pwph, *pwpl;
    cudaGetSymbolAddress(&pq,  g_q);   cudaGetSymbolAddress(&pk,  g_k);
    cudaGetSymbolAddress(&pv,  g_v);   cudaGetSymbolAddress(&pqt, g_qt);
    cudaGetSymbolAddress(&pkt, g_kt);  cudaGetSymbolAddress(&py,  g_y);
    cudaGetSymbolAddress(&pg,  g_gate);
    cudaGetSymbolAddress(&pxh, g_xh);  cudaGetSymbolAddress(&pxl, g_xl);
    cudaGetSymbolAddress(&pyh, g_yh);  cudaGetSymbolAddress(&pyl, g_yl);
    cudaGetSymbolAddress(&pwqh, g_wqh); cudaGetSymbolAddress(&pwql, g_wql);
    cudaGetSymbolAddress(&pwkh, g_wkh); cudaGetSymbolAddress(&pwkl, g_wkl);
    cudaGetSymbolAddress(&pwvh, g_wvh); cudaGetSymbolAddress(&pwvl, g_wvl);
    cudaGetSymbolAddress(&pwph, g_wph); cudaGetSymbolAddress(&pwpl, g_wpl);

    cudaFuncSetAttribute(gemm_mma<0>, cudaFuncAttributeMaxDynamicSharedMemorySize, GEMM_SMEM);
    cudaFuncSetAttribute(gemm_mma<1>, cudaFuncAttributeMaxDynamicSharedMemorySize, GEMM_SMEM);

    // 0) hi/lo splits
    split_kernel<<<M_*C_/1024, 256>>>(x, (__nv_bfloat16*)pxh, (__nv_bfloat16*)pxl, M_*C_);
    split_kernel<<<C_*C_/1024, 256>>>(Wq, (__nv_bfloat16*)pwqh, (__nv_bfloat16*)pwql, C_*C_);
    split_kernel<<<C_*C_/1024, 256>>>(Wk, (__nv_bfloat16*)pwkh, (__nv_bfloat16*)pwkl, C_*C_);
    split_kernel<<<C_*C_/1024, 256>>>(Wv, (__nv_bfloat16*)pwvh, (__nv_bfloat16*)pwvl, C_*C_);
    split_kernel<<<C_*C_/1024, 256>>>(Wproj, (__nv_bfloat16*)pwph, (__nv_bfloat16*)pwpl, C_*C_);

    // 1) gate
    gate_kernel<<<(M_ * H_ + 255) / 256, 256>>>(x, Wg, (float*)pg);

    // 2) q, k, v projections via mma.sync bf16 split
    dim3 ggrid(C_ / 128, M_ / 128);   // (16, 32)
    gemm_mma<0><<<ggrid, 256, GEMM_SMEM>>>((const __nv_bfloat16*)pxh, (const __nv_bfloat16*)pxl,
                                           (const __nv_bfloat16*)pwqh, (const __nv_bfloat16*)pwql,
                                           (float*)pq, nullptr, nullptr);
    gemm_mma<0><<<ggrid, 256, GEMM_SMEM>>>((const __nv_bfloat16*)pxh, (const __nv_bfloat16*)pxl,
                                           (const __nv_bfloat16*)pwkh, (const __nv_bfloat16*)pwkl,
                                           (float*)pk, nullptr, nullptr);
    gemm_mma<1><<<ggrid, 256, GEMM_SMEM>>>((const __nv_bfloat16*)pxh, (const __nv_bfloat16*)pxl,
                                           (const __nv_bfloat16*)pwvh, (const __nv_bfloat16*)pwvl,
                                           (float*)pv, ve, (const float*)pg);

    // 3) rope + rmsnorm (writes transposed [b][h][d][t])
    rope_kernel<<<8192, 256>>>((const float*)pq, (float*)pqt, cosp, sinp);
    rope_kernel<<<8192, 256>>>((const float*)pk, (float*)pkt, cosp, sinp);

    // 4) attention
    size_t smem = (size_t)(8192 * 3 + 64 * 65) * sizeof(float);
    cudaFuncSetAttribute(attn_kernel, cudaFuncAttributeMaxDynamicSharedMemorySize, (int)smem);
    attn_kernel<<<dim3(32, H_, B_), 256, smem>>>((const float*)pqt, (const float*)pkt,
                                                 (const float*)pv, (float*)py, winp);

    // 5) output projection via mma.sync bf16 split
    split_kernel<<<M_*C_/1024, 256>>>((const float*)py, (__nv_bfloat16*)pyh, (__nv_bfloat16*)pyl, M_*C_);
    gemm_mma<0><<<ggrid, 256, GEMM_SMEM>>>((const __nv_bfloat16*)pyh, (const __nv_bfloat16*)pyl,
                                           (const __nv_bfloat16*)pwph, (const __nv_bfloat16*)pwpl,
                                           out, nullptr, nullptr);
}

// round 4
// speedup vs baseline: 2.4452x; 1.3813x over previous
#include <cuda_runtime.h>
#include <cuda_bf16.h>
#include <math.h>
#include <stdint.h>

#define B_ 2
#define T_ 2048
#define C_ 2048
#define H_ 16
#define D_ 128
#define M_ (B_*T_)   // 4096 rows

// ---------------- scratch (device globals; no allocation allowed) -------------
__device__ float g_q [M_*C_];
__device__ float g_k [M_*C_];
__device__ float g_gate[M_*H_];

// bf16 hi/lo buffers
__device__ __nv_bfloat16 g_xh[M_*C_],  g_xl[M_*C_];
__device__ __nv_bfloat16 g_yh[M_*C_],  g_yl[M_*C_];
__device__ __nv_bfloat16 g_qh[M_*C_],  g_ql[M_*C_];   // [b][h][t][d]
__device__ __nv_bfloat16 g_kh[M_*C_],  g_kl[M_*C_];   // [b][h][t][d]
__device__ __nv_bfloat16 g_vh[M_*C_],  g_vl[M_*C_];   // [b][h][t][d]
__device__ __nv_bfloat16 g_wqh[C_*C_], g_wql[C_*C_];
__device__ __nv_bfloat16 g_wkh[C_*C_], g_wkl[C_*C_];
__device__ __nv_bfloat16 g_wvh[C_*C_], g_wvl[C_*C_];
__device__ __nv_bfloat16 g_wph[C_*C_], g_wpl[C_*C_];

// ================= PTX helpers =================
__device__ __forceinline__ uint32_t smem_u32(const void* p) {
    uint32_t a;
    asm("{ .reg .u64 t; cvta.to.shared.u64 t, %1; cvt.u32.u64 %0, t; }" : "=r"(a) : "l"(p));
    return a;
}
__device__ __forceinline__ void cpasync16(uint32_t saddr, const void* gaddr) {
    asm volatile("cp.async.cg.shared.global [%0], [%1], 16;" :: "r"(saddr), "l"(gaddr) : "memory");
}
__device__ __forceinline__ void ldsm4(uint32_t addr, uint32_t* r) {
    asm volatile("ldmatrix.sync.aligned.m8n8.x4.shared.b16 {%0,%1,%2,%3}, [%4];"
                 : "=r"(r[0]), "=r"(r[1]), "=r"(r[2]), "=r"(r[3]) : "r"(addr));
}
__device__ __forceinline__ void ldsm4t(uint32_t addr, uint32_t* r) {
    asm volatile("ldmatrix.sync.aligned.m8n8.x4.trans.shared.b16 {%0,%1,%2,%3}, [%4];"
                 : "=r"(r[0]), "=r"(r[1]), "=r"(r[2]), "=r"(r[3]) : "r"(addr));
}
__device__ __forceinline__ float ex2f(float x) {
    float y; asm("ex2.approx.f32 %0, %1;" : "=f"(y) : "f"(x)); return y;
}
#define MMA_BF16(Cf, Af, B0, B1)                                              \
    asm volatile("mma.sync.aligned.m16n8k16.row.col.f32.bf16.bf16.f32 "        \
        "{%0,%1,%2,%3},{%4,%5,%6,%7},{%8,%9},{%0,%1,%2,%3};"                   \
        : "+f"((Cf)[0]), "+f"((Cf)[1]), "+f"((Cf)[2]), "+f"((Cf)[3])           \
        : "r"((Af)[0]), "r"((Af)[1]), "r"((Af)[2]), "r"((Af)[3]),              \
          "r"(B0), "r"(B1))

__device__ __forceinline__ void store_hl(__nv_bfloat16* ph, __nv_bfloat16* pl,
                                         float a, float b) {
    __nv_bfloat16 ha = __float2bfloat16(a), hb = __float2bfloat16(b);
    *reinterpret_cast<__nv_bfloat162*>(ph) = __nv_bfloat162(ha, hb);
    *reinterpret_cast<__nv_bfloat162*>(pl) = __nv_bfloat162(
        __float2bfloat16(a - __bfloat162float(ha)),
        __float2bfloat16(b - __bfloat162float(hb)));
}
__device__ __forceinline__ void packhl(float a, float b, uint32_t& hi, uint32_t& lo) {
    __nv_bfloat16 ha = __float2bfloat16(a), hb = __float2bfloat16(b);
    __nv_bfloat162 hv(ha, hb);
    hi = *reinterpret_cast<uint32_t*>(&hv);
    __nv_bfloat162 lv(__float2bfloat16(a - __bfloat162float(ha)),
                      __float2bfloat16(b - __bfloat162float(hb)));
    lo = *reinterpret_cast<uint32_t*>(&lv);
}

// ---------------- fp32 -> bf16 hi/lo split ------------------------------------
__global__ void split_kernel(const float* __restrict__ src,
                             __nv_bfloat16* __restrict__ hi,
                             __nv_bfloat16* __restrict__ lo, int n) {
    int i = (blockIdx.x * blockDim.x + threadIdx.x) * 4;
    if (i >= n) return;
    float4 v = *(const float4*)(src + i);
    __nv_bfloat16 h0 = __float2bfloat16(v.x), h1 = __float2bfloat16(v.y);
    __nv_bfloat16 h2 = __float2bfloat16(v.z), h3 = __float2bfloat16(v.w);
    ((__nv_bfloat162*)(hi + i))[0] = __nv_bfloat162(h0, h1);
    ((__nv_bfloat162*)(hi + i))[1] = __nv_bfloat162(h2, h3);
    ((__nv_bfloat162*)(lo + i))[0] = __nv_bfloat162(
        __float2bfloat16(v.x - __bfloat162float(h0)),
        __float2bfloat16(v.y - __bfloat162float(h1)));
    ((__nv_bfloat162*)(lo + i))[1] = __nv_bfloat162(
        __float2bfloat16(v.z - __bfloat162float(h2)),
        __float2bfloat16(v.w - __bfloat162float(h3)));
}

// ---------------- gate = 3*sigmoid(x[:, :12] @ Wg^T) --------------------------
__global__ void gate_kernel(const float* __restrict__ x, const float* __restrict__ Wg,
                            float* __restrict__ gate) {
    int idx = blockIdx.x * blockDim.x + threadIdx.x;
    if (idx >= M_ * H_) return;
    int m = idx >> 4, h = idx & 15;
    float s = 0.f;
#pragma unroll
    for (int j = 0; j < 12; j++) s += x[(size_t)m * C_ + j] * Wg[h * 12 + j];
    gate[idx] = 3.f / (1.f + __expf(-s));
}

// ---------------- mma.sync bf16 split GEMM ------------------------------------
// EPI 0: plain fp32 output [m][n]
// EPI 2: v epilogue (acc + gate*ve) -> bf16 hi/lo at [b][h][t][d]
#define RS_B 80
#define ARR_B (128 * RS_B)
#define STG_B (4 * ARR_B)
#define NSTAGE 3
#define NCHUNK 64
#define GEMM_SMEM (NSTAGE * STG_B)

template<int EPI>
__global__ __launch_bounds__(256, 1) void gemm_mma(
    const __nv_bfloat16* __restrict__ Ah, const __nv_bfloat16* __restrict__ Al,
    const __nv_bfloat16* __restrict__ Bh, const __nv_bfloat16* __restrict__ Bl,
    float* __restrict__ Cout,
    __nv_bfloat16* __restrict__ Oh, __nv_bfloat16* __restrict__ Ol,
    const float* __restrict__ ve, const float* __restrict__ gate) {
    extern __shared__ char smc[];
    const uint32_t sb = smem_u32(smc);
    const int tid = threadIdx.x;
    const int wid = tid >> 5, lane = tid & 31;
    const int warp_m = wid & 3, warp_n = wid >> 2;
    const int arow0 = blockIdx.y * 128, brow0 = blockIdx.x * 128;

    auto load_chunk = [&](int stage, int chunk) {
        const int k0 = chunk * 32;
        uint32_t stg = sb + stage * STG_B;
#pragma unroll
        for (int j = 0; j < 8; j++) {
            int u = tid + j * 256;
            int arr = u >> 9;
            int rc = u & 511;
            int r = rc >> 2, c = rc & 3;
            uint32_t sa = stg + arr * ARR_B + r * RS_B + c * 16;
            const __nv_bfloat16* src;
            size_t off;
            if (arr < 2) {
                src = (arr == 0) ? Ah : Al;
                off = (size_t)(arow0 + r) * C_ + k0 + c * 8;
            } else {
                src = (arr == 2) ? Bh : Bl;
                off = (size_t)(brow0 + r) * C_ + k0 + c * 8;
            }
            cpasync16(sa, src + off);
        }
        asm volatile("cp.async.commit_group;" ::: "memory");
    };

    float acc[2][8][4];
#pragma unroll
    for (int mi = 0; mi < 2; mi++)
#pragma unroll
        for (int nf = 0; nf < 8; nf++)
#pragma unroll
            for (int q = 0; q < 4; q++) acc[mi][nf][q] = 0.f;

    load_chunk(0, 0);
    load_chunk(1, 1);

    const uint32_t a_lane_off = (uint32_t)((warp_m * 32 + (lane & 15)) * RS_B + (lane >> 4) * 16);
    const uint32_t b_lane_off = (uint32_t)((warp_n * 64 + (lane & 15)) * RS_B + (lane >> 4) * 16);

    for (int i = 0; i < NCHUNK; i++) {
        if (i < NCHUNK - 1) asm volatile("cp.async.wait_group 1;" ::: "memory");
        else                asm volatile("cp.async.wait_group 0;" ::: "memory");
        __syncthreads();
        if (i + 2 < NCHUNK) load_chunk((i + 2) % NSTAGE, i + 2);

        uint32_t stg = sb + (i % NSTAGE) * STG_B;
#pragma unroll
        for (int ks = 0; ks < 2; ks++) {
            uint32_t a_h[2][4], a_l[2][4];
            uint32_t b_h[8][2], b_l[8][2];
            uint32_t koff = ks * 32;
#pragma unroll
            for (int mi = 0; mi < 2; mi++) {
                ldsm4(stg + 0 * ARR_B + a_lane_off + mi * 16 * RS_B + koff, a_h[mi]);
                ldsm4(stg + 1 * ARR_B + a_lane_off + mi * 16 * RS_B + koff, a_l[mi]);
            }
#pragma unroll
            for (int nf4 = 0; nf4 < 4; nf4++) {
                uint32_t t[4];
                ldsm4(stg + 2 * ARR_B + b_lane_off + nf4 * 16 * RS_B + koff, t);
                b_h[nf4 * 2][0] = t[0]; b_h[nf4 * 2][1] = t[2];
                b_h[nf4 * 2 + 1][0] = t[1]; b_h[nf4 * 2 + 1][1] = t[3];
                ldsm4(stg + 3 * ARR_B + b_lane_off + nf4 * 16 * RS_B + koff, t);
                b_l[nf4 * 2][0] = t[0]; b_l[nf4 * 2][1] = t[2];
                b_l[nf4 * 2 + 1][0] = t[1]; b_l[nf4 * 2 + 1][1] = t[3];
            }
#pragma unroll
            for (int mi = 0; mi < 2; mi++)
#pragma unroll
                for (int nf = 0; nf < 8; nf++) {
                    MMA_BF16(acc[mi][nf], a_h[mi], b_h[nf][0], b_h[nf][1]);
                    MMA_BF16(acc[mi][nf], a_h[mi], b_l[nf][0], b_l[nf][1]);
                    MMA_BF16(acc[mi][nf], a_l[mi], b_h[nf][0], b_h[nf][1]);
                }
        }
    }

    const int r0w = arow0 + warp_m * 32 + (lane >> 2);
    const int c0w = brow0 + warp_n * 64 + (lane & 3) * 2;
#pragma unroll
    for (int mi = 0; mi < 2; mi++) {
#pragma unroll
        for (int nf = 0; nf < 8; nf++) {
            int n = c0w + nf * 8;
            int m0 = r0w + mi * 16;
            int m1 = m0 + 8;
            float v0 = acc[mi][nf][0], v1 = acc[mi][nf][1];
            float v2 = acc[mi][nf][2], v3 = acc[mi][nf][3];
            if (EPI == 2) {
                float g0 = gate[m0 * H_ + (n >> 7)];
                float g1 = gate[m1 * H_ + (n >> 7)];
                const float* ve0 = ve + (size_t)m0 * C_ + n;
                const float* ve1 = ve + (size_t)m1 * C_ + n;
                v0 += g0 * ve0[0]; v1 += g0 * ve0[1];
                v2 += g1 * ve1[0]; v3 += g1 * ve1[1];
                int hh = n >> 7, dd = n & 127;
                size_t o0 = ((size_t)((m0 >> 11) * H_ + hh) * T_ + (m0 & 2047)) * D_ + dd;
                size_t o1 = ((size_t)((m1 >> 11) * H_ + hh) * T_ + (m1 & 2047)) * D_ + dd;
                store_hl(Oh + o0, Ol + o0, v0, v1);
                store_hl(Oh + o1, Ol + o1, v2, v3);
            } else {
                *(float2*)(Cout + (size_t)m0 * C_ + n) = make_float2(v0, v1);
                *(float2*)(Cout + (size_t)m1 * C_ + n) = make_float2(v2, v3);
            }
        }
    }
}

// ---------------- RoPE + RMSnorm (+1.2), writes bf16 hi/lo [b][h][t][d] -------
__global__ void rope_split(const float* __restrict__ src,
                           __nv_bfloat16* __restrict__ dh, __nv_bfloat16* __restrict__ dl,
                           const float* __restrict__ cosp, const float* __restrict__ sinp) {
    int wi = blockIdx.x * 8 + (threadIdx.x >> 5);
    int l = threadIdx.x & 31;
    int m = wi >> 4, h = wi & 15;
    int b = m >> 11, t = m & 2047;
    const float* row = src + (size_t)m * C_ + h * D_;
    int d0 = l * 2;
    float2 xa = *(const float2*)(row + d0);
    float2 xb = *(const float2*)(row + d0 + 64);
    float2 cc = *(const float2*)(cosp + t * 64 + d0);
    float2 sn = *(const float2*)(sinp + t * 64 + d0);
    float y1a = xa.x * cc.x + xb.x * sn.x;
    float y1b = xa.y * cc.y + xb.y * sn.y;
    float y2a = xb.x * cc.x - xa.x * sn.x;
    float y2b = xb.y * cc.y - xa.y * sn.y;
    float ss = y1a * y1a + y1b * y1b + y2a * y2a + y2b * y2b;
#pragma unroll
    for (int off = 16; off; off >>= 1) ss += __shfl_xor_sync(0xffffffffu, ss, off);
    float r = rsqrtf(ss * (1.f / 128.f) + 1e-6f) * 1.2f;
    size_t ob = ((size_t)(b * H_ + h) * T_ + t) * D_;
    store_hl(dh + ob + d0, dl + ob + d0, y1a * r, y1b * r);
    store_hl(dh + ob + d0 + 64, dl + ob + d0 + 64, y2a * r, y2b * r);
}

// ---------------- tensor-core flash attention (bf16 hi/lo split) -------------
// block: 128 threads (4 warps), each warp owns 16 q rows of the 64-row q tile.
// smem: Qh|Ql (resident) + 2 stages of (Kh|Kl|Vh|Vl), row stride 272 B.
#define TILE_B 17408                 // 64 rows * 272 B
#define KV_OFF (2*TILE_B)
#define STG (4*TILE_B)
#define ATT_SMEM (2*TILE_B + 2*STG)  // 174080

__global__ __launch_bounds__(128, 1) void attn_mma(
    const __nv_bfloat16* __restrict__ qh, const __nv_bfloat16* __restrict__ ql,
    const __nv_bfloat16* __restrict__ kh, const __nv_bfloat16* __restrict__ kl,
    const __nv_bfloat16* __restrict__ vh, const __nv_bfloat16* __restrict__ vl,
    __nv_bfloat16* __restrict__ yh, __nv_bfloat16* __restrict__ yl,
    const int* __restrict__ winp) {
    extern __shared__ char smc[];
    const uint32_t sb = smem_u32(smc);
    const int tid = threadIdx.x, w = tid >> 5, l = tid & 31;
    const int t0 = blockIdx.x * 64, h = blockIdx.y, b = blockIdx.z;
    int win = *winp;
    if (win <= 0 || win >= T_) win = T_;
    const size_t hb = (size_t)(b * H_ + h) * ((size_t)T_ * D_);

    // Q tiles (hi, lo)
#pragma unroll
    for (int j = 0; j < 8; j++) {
        int u = tid + j * 128;
        int r = u >> 4, c = u & 15;
        uint32_t so = (uint32_t)(r * 272 + c * 16);
        size_t go = hb + (size_t)(t0 + r) * D_ + c * 8;
        cpasync16(sb + so, qh + go);
        cpasync16(sb + TILE_B + so, ql + go);
    }
    asm volatile("cp.async.commit_group;" ::: "memory");

    int start = t0 - win;
    if (start < 0) start = 0;
    start &= ~63;
    const int ntile = ((t0 - start) >> 6) + 1;

    auto loadKV = [&](int stg, int k0) {
        uint32_t bs = sb + KV_OFF + stg * STG;
#pragma unroll
        for (int j = 0; j < 8; j++) {
            int u = tid + j * 128;
            int r = u >> 4, c = u & 15;
            uint32_t so = (uint32_t)(r * 272 + c * 16);
            size_t go = hb + (size_t)(k0 + r) * D_ + c * 8;
            cpasync16(bs + so, kh + go);
            cpasync16(bs + TILE_B + so, kl + go);
            cpasync16(bs + 2 * TILE_B + so, vh + go);
            cpasync16(bs + 3 * TILE_B + so, vl + go);
        }
        asm volatile("cp.async.commit_group;" ::: "memory");
    };
    loadKV(0, start);
    if (ntile > 1) loadKV(1, start + 64);

    float o[16][4];
#pragma unroll
    for (int f = 0; f < 16; f++)
#pragma unroll
        for (int q = 0; q < 4; q++) o[f][q] = 0.f;
    float rm0 = -1e4f, rm1 = -1e4f, rl0 = 0.f, rl1 = 0.f;
    const float SC2 = 0.1275187989f;   // 1/sqrt(128) * log2(e)

    const uint32_t aoff = (uint32_t)((w * 16 + (l & 15)) * 272 + (l >> 4) * 16);
    const uint32_t boff = (uint32_t)((l & 15) * 272 + (l >> 4) * 16);
    const int r0 = t0 + w * 16 + (l >> 2), r1 = r0 + 8;

    for (int i = 0; i < ntile; i++) {
        int k0 = start + i * 64;
        if (i + 1 < ntile) asm volatile("cp.async.wait_group 1;" ::: "memory");
        else               asm volatile("cp.async.wait_group 0;" ::: "memory");
        __syncthreads();
        uint32_t bs = sb + KV_OFF + (i & 1) * STG;

        // ---- S = Qh*Kh + Qh*Kl + Ql*Kh ----
        float s[8][4];
#pragma unroll
        for (int f = 0; f < 8; f++)
#pragma unroll
            for (int q = 0; q < 4; q++) s[f][q] = 0.f;
#pragma unroll
        for (int ks = 0; ks < 8; ks++) {
            uint32_t aq[4], al4[4];
            ldsm4(sb + aoff + ks * 32, aq);
            ldsm4(sb + TILE_B + aoff + ks * 32, al4);
#pragma unroll
            for (int ng = 0; ng < 4; ng++) {
                uint32_t tk[4], uk[4];
                ldsm4(bs + boff + ng * 16 * 272 + ks * 32, tk);
                ldsm4(bs + TILE_B + boff + ng * 16 * 272 + ks * 32, uk);
                MMA_BF16(s[ng * 2], aq, tk[0], tk[2]);
                MMA_BF16(s[ng * 2], aq, uk[0], uk[2]);
                MMA_BF16(s[ng * 2], al4, tk[0], tk[2]);
                MMA_BF16(s[ng * 2 + 1], aq, tk[1], tk[3]);
                MMA_BF16(s[ng * 2 + 1], aq, uk[1], uk[3]);
                MMA_BF16(s[ng * 2 + 1], al4, tk[1], tk[3]);
            }
        }

        // ---- masked online softmax (exp2 domain) ----
        float mx0 = -1e30f, mx1 = -1e30f;
#pragma unroll
        for (int nf = 0; nf < 8; nf++) {
            int c0 = k0 + nf * 8 + (l & 3) * 2, c1 = c0 + 1;
            float x0 = (c0 <= r0 && r0 - c0 <= win) ? s[nf][0] * SC2 : -1e30f;
            float x1 = (c1 <= r0 && r0 - c1 <= win) ? s[nf][1] * SC2 : -1e30f;
            float x2 = (c0 <= r1 && r1 - c0 <= win) ? s[nf][2] * SC2 : -1e30f;
            float x3 = (c1 <= r1 && r1 - c1 <= win) ? s[nf][3] * SC2 : -1e30f;
            s[nf][0] = x0; s[nf][1] = x1; s[nf][2] = x2; s[nf][3] = x3;
            mx0 = fmaxf(mx0, fmaxf(x0, x1));
            mx1 = fmaxf(mx1, fmaxf(x2, x3));
        }
        mx0 = fmaxf(mx0, __shfl_xor_sync(0xffffffffu, mx0, 1));
        mx0 = fmaxf(mx0, __shfl_xor_sync(0xffffffffu, mx0, 2));
        mx1 = fmaxf(mx1, __shfl_xor_sync(0xffffffffu, mx1, 1));
        mx1 = fmaxf(mx1, __shfl_xor_sync(0xffffffffu, mx1, 2));
        float mn0 = fmaxf(rm0, fmaxf(mx0, -1e4f));
        float mn1 = fmaxf(rm1, fmaxf(mx1, -1e4f));
        float corr0 = ex2f(rm0 - mn0), corr1 = ex2f(rm1 - mn1);
        float ls0 = 0.f, ls1 = 0.f;
#pragma unroll
        for (int nf = 0; nf < 8; nf++) {
            float p0 = ex2f(s[nf][0] - mn0);
            float p1 = ex2f(s[nf][1] - mn0);
            float p2 = ex2f(s[nf][2] - mn1);
            float p3 = ex2f(s[nf][3] - mn1);
            s[nf][0] = p0; s[nf][1] = p1; s[nf][2] = p2; s[nf][3] = p3;
            ls0 += p0 + p1; ls1 += p2 + p3;
        }
        ls0 += __shfl_xor_sync(0xffffffffu, ls0, 1);
        ls0 += __shfl_xor_sync(0xffffffffu, ls0, 2);
        ls1 += __shfl_xor_sync(0xffffffffu, ls1, 1);
        ls1 += __shfl_xor_sync(0xffffffffu, ls1, 2);
        rl0 = rl0 * corr0 + ls0;
        rl1 = rl1 * corr1 + ls1;
        rm0 = mn0; rm1 = mn1;
#pragma unroll
        for (int f = 0; f < 16; f++) {
            o[f][0] *= corr0; o[f][1] *= corr0;
            o[f][2] *= corr1; o[f][3] *= corr1;
        }

        // ---- O += Ph*Vh + Ph*Vl + Pl*Vh ----
#pragma unroll
        for (int ks = 0; ks < 4; ks++) {
            uint32_t ph[4], pl4[4];
            packhl(s[2 * ks][0], s[2 * ks][1], ph[0], pl4[0]);
            packhl(s[2 * ks][2], s[2 * ks][3], ph[1], pl4[1]);
            packhl(s[2 * ks + 1][0], s[2 * ks + 1][1], ph[2], pl4[2]);
            packhl(s[2 * ks + 1][2], s[2 * ks + 1][3], ph[3], pl4[3]);
            uint32_t voff = (uint32_t)((ks * 16 + (l & 15)) * 272 + (l >> 4) * 16);
#pragma unroll
            for (int dg = 0; dg < 8; dg++) {
                uint32_t tv[4], uv[4];
                ldsm4t(bs + 2 * TILE_B + voff + dg * 32, tv);
                ldsm4t(bs + 3 * TILE_B + voff + dg * 32, uv);
                MMA_BF16(o[dg * 2], ph, tv[0], tv[1]);
                MMA_BF16(o[dg * 2], ph, uv[0], uv[1]);
                MMA_BF16(o[dg * 2], pl4, tv[0], tv[1]);
                MMA_BF16(o[dg * 2 + 1], ph, tv[2], tv[3]);
                MMA_BF16(o[dg * 2 + 1], ph, uv[2], uv[3]);
                MMA_BF16(o[dg * 2 + 1], pl4, tv[2], tv[3]);
            }
        }
        __syncthreads();
        if (i + 2 < ntile) loadKV(i & 1, k0 + 128);
    }

    // ---- epilogue: normalize, write bf16 hi/lo y [m][h*128+d] ----
    float i0 = 1.f / rl0, i1 = 1.f / rl1;
    int m0r = t0 + w * 16 + (l >> 2);
#pragma unroll
    for (int f = 0; f < 16; f++) {
        int col = h * 128 + (f >> 1) * 16 + (f & 1) * 8 + (l & 3) * 2;
        size_t a0 = ((size_t)(b * T_ + m0r)) * C_ + col;
        size_t a1 = a0 + (size_t)8 * C_;
        store_hl(yh + a0, yl + a0, o[f][0] * i0, o[f][1] * i0);
        store_hl(yh + a1, yl + a1, o[f][2] * i1, o[f][3] * i1);
    }
}

// ---------------- launch ------------------------------------------------------
extern "C" void kernel_launch(void* const* d_in, const int* in_sizes, int n_in,
                              void* d_out, int out_size) {
    const float* x     = (const float*)d_in[0];
    const float* ve    = (const float*)d_in[1];
    const float* Wq    = (const float*)d_in[2];
    const float* Wk    = (const float*)d_in[3];
    const float* Wv    = (const float*)d_in[4];
    const float* Wproj = (const float*)d_in[5];
    const float* Wg    = (const float*)d_in[6];
    const float* cosp  = (const float*)d_in[7];
    const float* sinp  = (const float*)d_in[8];
    const int*   winp  = (const int*)d_in[9];
    float* out = (float*)d_out;

    void *pq, *pk, *pg, *pxh, *pxl, *pyh, *pyl;
    void *pqh, *pql, *pkh, *pkl, *pvh, *pvl;
    void *pwqh, *pwql, *pwkh, *pwkl, *pwvh, *pwvl, *pwph, *pwpl;
    cudaGetSymbolAddress(&pq,  g_q);   cudaGetSymbolAddress(&pk,  g_k);
    cudaGetSymbolAddress(&pg,  g_gate);
    cudaGetSymbolAddress(&pxh, g_xh);  cudaGetSymbolAddress(&pxl, g_xl);
    cudaGetSymbolAddress(&pyh, g_yh);  cudaGetSymbolAddress(&pyl, g_yl);
    cudaGetSymbolAddress(&pqh, g_qh);  cudaGetSymbolAddress(&pql, g_ql);
    cudaGetSymbolAddress(&pkh, g_kh);  cudaGetSymbolAddress(&pkl, g_kl);
    cudaGetSymbolAddress(&pvh, g_vh);  cudaGetSymbolAddress(&pvl, g_vl);
    cudaGetSymbolAddress(&pwqh, g_wqh); cudaGetSymbolAddress(&pwql, g_wql);
    cudaGetSymbolAddress(&pwkh, g_wkh); cudaGetSymbolAddress(&pwkl, g_wkl);
    cudaGetSymbolAddress(&pwvh, g_wvh); cudaGetSymbolAddress(&pwvl, g_wvl);
    cudaGetSymbolAddress(&pwph, g_wph); cudaGetSymbolAddress(&pwpl, g_wpl);

    cudaFuncSetAttribute(gemm_mma<0>, cudaFuncAttributeMaxDynamicSharedMemorySize, GEMM_SMEM);
    cudaFuncSetAttribute(gemm_mma<2>, cudaFuncAttributeMaxDynamicSharedMemorySize, GEMM_SMEM);
    cudaFuncSetAttribute(attn_mma, cudaFuncAttributeMaxDynamicSharedMemorySize, ATT_SMEM);

    // 0) hi/lo splits
    split_kernel<<<M_*C_/1024, 256>>>(x, (__nv_bfloat16*)pxh, (__nv_bfloat16*)pxl, M_*C_);
    split_kernel<<<C_*C_/1024, 256>>>(Wq, (__nv_bfloat16*)pwqh, (__nv_bfloat16*)pwql, C_*C_);
    split_kernel<<<C_*C_/1024, 256>>>(Wk, (__nv_bfloat16*)pwkh, (__nv_bfloat16*)pwkl, C_*C_);
    split_kernel<<<C_*C_/1024, 256>>>(Wv, (__nv_bfloat16*)pwvh, (__nv_bfloat16*)pwvl, C_*C_);
    split_kernel<<<C_*C_/1024, 256>>>(Wproj, (__nv_bfloat16*)pwph, (__nv_bfloat16*)pwpl, C_*C_);

    // 1) gate
    gate_kernel<<<(M_ * H_ + 255) / 256, 256>>>(x, Wg, (float*)pg);

    // 2) q, k, v projections
    dim3 ggrid(C_ / 128, M_ / 128);
    gemm_mma<0><<<ggrid, 256, GEMM_SMEM>>>((const __nv_bfloat16*)pxh, (const __nv_bfloat16*)pxl,
                                           (const __nv_bfloat16*)pwqh, (const __nv_bfloat16*)pwql,
                                           (float*)pq, nullptr, nullptr, nullptr, nullptr);
    gemm_mma<0><<<ggrid, 256, GEMM_SMEM>>>((const __nv_bfloat16*)pxh, (const __nv_bfloat16*)pxl,
                                           (const __nv_bfloat16*)pwkh, (const __nv_bfloat16*)pwkl,
                                           (float*)pk, nullptr, nullptr, nullptr, nullptr);
    gemm_mma<2><<<ggrid, 256, GEMM_SMEM>>>((const __nv_bfloat16*)pxh, (const __nv_bfloat16*)pxl,
                                           (const __nv_bfloat16*)pwvh, (const __nv_bfloat16*)pwvl,
                                           nullptr, (__nv_bfloat16*)pvh, (__nv_bfloat16*)pvl,
                                           ve, (const float*)pg);

    // 3) rope + rmsnorm -> bf16 hi/lo [b,h,t,d]
    rope_split<<<8192, 256>>>((const float*)pq, (__nv_bfloat16*)pqh, (__nv_bfloat16*)pql, cosp, sinp);
    rope_split<<<8192, 256>>>((const float*)pk, (__nv_bfloat16*)pkh, (__nv_bfloat16*)pkl, cosp, sinp);

    // 4) tensor-core attention -> bf16 hi/lo y
    attn_mma<<<dim3(T_ / 64, H_, B_), 128, ATT_SMEM>>>(
        (const __nv_bfloat16*)pqh, (const __nv_bfloat16*)pql,
        (const __nv_bfloat16*)pkh, (const __nv_bfloat16*)pkl,
        (const __nv_bfloat16*)pvh, (const __nv_bfloat16*)pvl,
        (__nv_bfloat16*)pyh, (__nv_bfloat16*)pyl, winp);

    // 5) output projection
    gemm_mma<0><<<ggrid, 256, GEMM_SMEM>>>((const __nv_bfloat16*)pyh, (const __nv_bfloat16*)pyl,
                                           (const __nv_bfloat16*)pwph, (const __nv_bfloat16*)pwpl,
                                           out, nullptr, nullptr, nullptr, nullptr);
}

// round 5
// speedup vs baseline: 2.7450x; 1.1226x over previous
#include <cuda_runtime.h>
#include <cuda_bf16.h>
#include <math.h>
#include <stdint.h>

#define B_ 2
#define T_ 2048
#define C_ 2048
#define H_ 16
#define D_ 128
#define M_ (B_*T_)   // 4096 rows

// ---------------- scratch (device globals; no allocation allowed) -------------
__device__ float g_gate[M_*H_];
__device__ __nv_bfloat16 g_xh[M_*C_],  g_xl[M_*C_];
__device__ __nv_bfloat16 g_yh[M_*C_],  g_yl[M_*C_];
__device__ __nv_bfloat16 g_qh[M_*C_],  g_ql[M_*C_];   // [b][h][t][d]
__device__ __nv_bfloat16 g_kh[M_*C_],  g_kl[M_*C_];   // [b][h][t][d]
__device__ __nv_bfloat16 g_vh[M_*C_],  g_vl[M_*C_];   // [b][h][t][d]
__device__ __nv_bfloat16 g_wqh[C_*C_], g_wql[C_*C_];
__device__ __nv_bfloat16 g_wkh[C_*C_], g_wkl[C_*C_];
__device__ __nv_bfloat16 g_wvh[C_*C_], g_wvl[C_*C_];
__device__ __nv_bfloat16 g_wph[C_*C_], g_wpl[C_*C_];

// ================= PTX helpers =================
__device__ __forceinline__ uint32_t smem_u32(const void* p) {
    uint32_t a;
    asm("{ .reg .u64 t; cvta.to.shared.u64 t, %1; cvt.u32.u64 %0, t; }" : "=r"(a) : "l"(p));
    return a;
}
__device__ __forceinline__ void cpasync16(uint32_t saddr, const void* gaddr) {
    asm volatile("cp.async.cg.shared.global [%0], [%1], 16;" :: "r"(saddr), "l"(gaddr) : "memory");
}
__device__ __forceinline__ void ldsm4(uint32_t addr, uint32_t* r) {
    asm volatile("ldmatrix.sync.aligned.m8n8.x4.shared.b16 {%0,%1,%2,%3}, [%4];"
                 : "=r"(r[0]), "=r"(r[1]), "=r"(r[2]), "=r"(r[3]) : "r"(addr));
}
__device__ __forceinline__ void ldsm4t(uint32_t addr, uint32_t* r) {
    asm volatile("ldmatrix.sync.aligned.m8n8.x4.trans.shared.b16 {%0,%1,%2,%3}, [%4];"
                 : "=r"(r[0]), "=r"(r[1]), "=r"(r[2]), "=r"(r[3]) : "r"(addr));
}
__device__ __forceinline__ float ex2f(float x) {
    float y; asm("ex2.approx.f32 %0, %1;" : "=f"(y) : "f"(x)); return y;
}
#define MMA_BF16(Cf, Af, B0, B1)                                              \
    asm volatile("mma.sync.aligned.m16n8k16.row.col.f32.bf16.bf16.f32 "        \
        "{%0,%1,%2,%3},{%4,%5,%6,%7},{%8,%9},{%0,%1,%2,%3};"                   \
        : "+f"((Cf)[0]), "+f"((Cf)[1]), "+f"((Cf)[2]), "+f"((Cf)[3])           \
        : "r"((Af)[0]), "r"((Af)[1]), "r"((Af)[2]), "r"((Af)[3]),              \
          "r"(B0), "r"(B1))

__device__ __forceinline__ void store_hl(__nv_bfloat16* ph, __nv_bfloat16* pl,
                                         float a, float b) {
    __nv_bfloat16 ha = __float2bfloat16(a), hb = __float2bfloat16(b);
    *reinterpret_cast<__nv_bfloat162*>(ph) = __nv_bfloat162(ha, hb);
    *reinterpret_cast<__nv_bfloat162*>(pl) = __nv_bfloat162(
        __float2bfloat16(a - __bfloat162float(ha)),
        __float2bfloat16(b - __bfloat162float(hb)));
}
__device__ __forceinline__ void packhl(float a, float b, uint32_t& hi, uint32_t& lo) {
    __nv_bfloat16 ha = __float2bfloat16(a), hb = __float2bfloat16(b);
    __nv_bfloat162 hv(ha, hb);
    hi = *reinterpret_cast<uint32_t*>(&hv);
    __nv_bfloat162 lv(__float2bfloat16(a - __bfloat162float(ha)),
                      __float2bfloat16(b - __bfloat162float(hb)));
    lo = *reinterpret_cast<uint32_t*>(&lv);
}

// ---------------- fp32 -> bf16 hi/lo split ------------------------------------
__global__ void split_kernel(const float* __restrict__ src,
                             __nv_bfloat16* __restrict__ hi,
                             __nv_bfloat16* __restrict__ lo, int n) {
    int i = (blockIdx.x * blockDim.x + threadIdx.x) * 4;
    if (i >= n) return;
    float4 v = *(const float4*)(src + i);
    __nv_bfloat16 h0 = __float2bfloat16(v.x), h1 = __float2bfloat16(v.y);
    __nv_bfloat16 h2 = __float2bfloat16(v.z), h3 = __float2bfloat16(v.w);
    ((__nv_bfloat162*)(hi + i))[0] = __nv_bfloat162(h0, h1);
    ((__nv_bfloat162*)(hi + i))[1] = __nv_bfloat162(h2, h3);
    ((__nv_bfloat162*)(lo + i))[0] = __nv_bfloat162(
        __float2bfloat16(v.x - __bfloat162float(h0)),
        __float2bfloat16(v.y - __bfloat162float(h1)));
    ((__nv_bfloat162*)(lo + i))[1] = __nv_bfloat162(
        __float2bfloat16(v.z - __bfloat162float(h2)),
        __float2bfloat16(v.w - __bfloat162float(h3)));
}

// batched weight split: blockIdx.y selects which weight
__global__ void wsplit_kernel(const float* __restrict__ w0, const float* __restrict__ w1,
                              const float* __restrict__ w2, const float* __restrict__ w3,
                              __nv_bfloat16* __restrict__ h0, __nv_bfloat16* __restrict__ l0,
                              __nv_bfloat16* __restrict__ h1, __nv_bfloat16* __restrict__ l1,
                              __nv_bfloat16* __restrict__ h2, __nv_bfloat16* __restrict__ l2,
                              __nv_bfloat16* __restrict__ h3, __nv_bfloat16* __restrict__ l3) {
    const float* src; __nv_bfloat16 *hi, *lo;
    switch (blockIdx.y) {
        case 0: src = w0; hi = h0; lo = l0; break;
        case 1: src = w1; hi = h1; lo = l1; break;
        case 2: src = w2; hi = h2; lo = l2; break;
        default: src = w3; hi = h3; lo = l3; break;
    }
    int i = (blockIdx.x * blockDim.x + threadIdx.x) * 4;
    float4 v = *(const float4*)(src + i);
    __nv_bfloat16 a0 = __float2bfloat16(v.x), a1 = __float2bfloat16(v.y);
    __nv_bfloat16 a2 = __float2bfloat16(v.z), a3 = __float2bfloat16(v.w);
    ((__nv_bfloat162*)(hi + i))[0] = __nv_bfloat162(a0, a1);
    ((__nv_bfloat162*)(hi + i))[1] = __nv_bfloat162(a2, a3);
    ((__nv_bfloat162*)(lo + i))[0] = __nv_bfloat162(
        __float2bfloat16(v.x - __bfloat162float(a0)),
        __float2bfloat16(v.y - __bfloat162float(a1)));
    ((__nv_bfloat162*)(lo + i))[1] = __nv_bfloat162(
        __float2bfloat16(v.z - __bfloat162float(a2)),
        __float2bfloat16(v.w - __bfloat162float(a3)));
}

// ---------------- gate = 3*sigmoid(x[:, :12] @ Wg^T) --------------------------
__global__ void gate_kernel(const float* __restrict__ x, const float* __restrict__ Wg,
                            float* __restrict__ gate) {
    int idx = blockIdx.x * blockDim.x + threadIdx.x;
    if (idx >= M_ * H_) return;
    int m = idx >> 4, h = idx & 15;
    float s = 0.f;
#pragma unroll
    for (int j = 0; j < 12; j++) s += x[(size_t)m * C_ + j] * Wg[h * 12 + j];
    gate[idx] = 3.f / (1.f + __expf(-s));
}

// ---------------- mma.sync bf16 split GEMM ------------------------------------
// EPI 0: fp32 out. EPI 1: rope+rms+split -> bf16 hi/lo [b,h,t,d].
// EPI 2: v epilogue (acc + gate*ve) -> bf16 hi/lo [b,h,t,d].
// 2-stage cp.async, 2 CTAs/SM, product-major MMA ordering.
#define RS_B 80
#define ARR_B (128 * RS_B)
#define STG_B (4 * ARR_B)           // 40960
#define NSTAGE 2
#define NCHUNK 64
#define GEMM_SMEM (NSTAGE * STG_B)  // 81920

template<int EPI>
__global__ __launch_bounds__(256, 2) void gemm_mma(
    const __nv_bfloat16* __restrict__ Ah, const __nv_bfloat16* __restrict__ Al,
    const __nv_bfloat16* __restrict__ Bh, const __nv_bfloat16* __restrict__ Bl,
    float* __restrict__ Cout,
    __nv_bfloat16* __restrict__ Oh, __nv_bfloat16* __restrict__ Ol,
    const float* __restrict__ ve, const float* __restrict__ gate,
    const float* __restrict__ cosp, const float* __restrict__ sinp) {
    extern __shared__ char smc[];
    const uint32_t sb = smem_u32(smc);
    const int tid = threadIdx.x;
    const int wid = tid >> 5, lane = tid & 31;
    const int warp_m = wid & 3, warp_n = wid >> 2;
    const int arow0 = blockIdx.y * 128, brow0 = blockIdx.x * 128;

    auto load_chunk = [&](int stage, int chunk) {
        const int k0 = chunk * 32;
        uint32_t stg = sb + stage * STG_B;
#pragma unroll
        for (int j = 0; j < 8; j++) {
            int u = tid + j * 256;
            int arr = u >> 9;
            int rc = u & 511;
            int r = rc >> 2, c = rc & 3;
            uint32_t sa = stg + arr * ARR_B + r * RS_B + c * 16;
            const __nv_bfloat16* src;
            size_t off;
            if (arr < 2) {
                src = (arr == 0) ? Ah : Al;
                off = (size_t)(arow0 + r) * C_ + k0 + c * 8;
            } else {
                src = (arr == 2) ? Bh : Bl;
                off = (size_t)(brow0 + r) * C_ + k0 + c * 8;
            }
            cpasync16(sa, src + off);
        }
        asm volatile("cp.async.commit_group;" ::: "memory");
    };

    float acc[2][8][4];
#pragma unroll
    for (int mi = 0; mi < 2; mi++)
#pragma unroll
        for (int nf = 0; nf < 8; nf++)
#pragma unroll
            for (int q = 0; q < 4; q++) acc[mi][nf][q] = 0.f;

    load_chunk(0, 0);

    const uint32_t a_lane_off = (uint32_t)((warp_m * 32 + (lane & 15)) * RS_B + (lane >> 4) * 16);
    const uint32_t b_lane_off = (uint32_t)((warp_n * 64 + (lane & 15)) * RS_B + (lane >> 4) * 16);

    for (int i = 0; i < NCHUNK; i++) {
        asm volatile("cp.async.wait_group 0;" ::: "memory");
        __syncthreads();
        if (i + 1 < NCHUNK) load_chunk((i + 1) & 1, i + 1);

        uint32_t stg = sb + (i & 1) * STG_B;
#pragma unroll
        for (int ks = 0; ks < 2; ks++) {
            uint32_t a_h[2][4], a_l[2][4];
            uint32_t b_h[8][2], b_l[8][2];
            uint32_t koff = ks * 32;
#pragma unroll
            for (int mi = 0; mi < 2; mi++) {
                ldsm4(stg + 0 * ARR_B + a_lane_off + mi * 16 * RS_B + koff, a_h[mi]);
                ldsm4(stg + 1 * ARR_B + a_lane_off + mi * 16 * RS_B + koff, a_l[mi]);
            }
#pragma unroll
            for (int nf4 = 0; nf4 < 4; nf4++) {
                uint32_t t[4];
                ldsm4(stg + 2 * ARR_B + b_lane_off + nf4 * 16 * RS_B + koff, t);
                b_h[nf4 * 2][0] = t[0]; b_h[nf4 * 2][1] = t[2];
                b_h[nf4 * 2 + 1][0] = t[1]; b_h[nf4 * 2 + 1][1] = t[3];
                ldsm4(stg + 3 * ARR_B + b_lane_off + nf4 * 16 * RS_B + koff, t);
                b_l[nf4 * 2][0] = t[0]; b_l[nf4 * 2][1] = t[2];
                b_l[nf4 * 2 + 1][0] = t[1]; b_l[nf4 * 2 + 1][1] = t[3];
            }
            // product-major: same-acc reuse distance = 8
#pragma unroll
            for (int mi = 0; mi < 2; mi++) {
#pragma unroll
                for (int nf = 0; nf < 8; nf++) MMA_BF16(acc[mi][nf], a_h[mi], b_h[nf][0], b_h[nf][1]);
#pragma unroll
                for (int nf = 0; nf < 8; nf++) MMA_BF16(acc[mi][nf], a_h[mi], b_l[nf][0], b_l[nf][1]);
#pragma unroll
                for (int nf = 0; nf < 8; nf++) MMA_BF16(acc[mi][nf], a_l[mi], b_h[nf][0], b_h[nf][1]);
            }
        }
    }

    if (EPI == 1) {
        // stage acc tile to smem, then rope+rms+split per row
        __syncthreads();
        float* S = (float*)smc;      // 128 x 132
        const int rbase = warp_m * 32 + (lane >> 2);
        const int cbase = warp_n * 64 + (lane & 3) * 2;
#pragma unroll
        for (int mi = 0; mi < 2; mi++)
#pragma unroll
            for (int nf = 0; nf < 8; nf++) {
                int r = rbase + mi * 16, c = cbase + nf * 8;
                S[r * 132 + c] = acc[mi][nf][0];
                S[r * 132 + c + 1] = acc[mi][nf][1];
                S[(r + 8) * 132 + c] = acc[mi][nf][2];
                S[(r + 8) * 132 + c + 1] = acc[mi][nf][3];
            }
        __syncthreads();
        const int hh = brow0 >> 7;
        const int d0 = lane * 2;
#pragma unroll 4
        for (int rr = wid * 16; rr < wid * 16 + 16; rr++) {
            int m = arow0 + rr, b = m >> 11, t = m & 2047;
            float xa0 = S[rr * 132 + d0],      xa1 = S[rr * 132 + d0 + 1];
            float xb0 = S[rr * 132 + d0 + 64], xb1 = S[rr * 132 + d0 + 65];
            float2 cc = *(const float2*)(cosp + t * 64 + d0);
            float2 sn = *(const float2*)(sinp + t * 64 + d0);
            float y1a = xa0 * cc.x + xb0 * sn.x;
            float y1b = xa1 * cc.y + xb1 * sn.y;
            float y2a = xb0 * cc.x - xa0 * sn.x;
            float y2b = xb1 * cc.y - xa1 * sn.y;
            float ss = y1a * y1a + y1b * y1b + y2a * y2a + y2b * y2b;
#pragma unroll
            for (int off = 16; off; off >>= 1) ss += __shfl_xor_sync(0xffffffffu, ss, off);
            float r = rsqrtf(ss * (1.f / 128.f) + 1e-6f) * 1.2f;
            size_t ob = ((size_t)(b * H_ + hh) * T_ + t) * D_;
            store_hl(Oh + ob + d0, Ol + ob + d0, y1a * r, y1b * r);
            store_hl(Oh + ob + d0 + 64, Ol + ob + d0 + 64, y2a * r, y2b * r);
        }
        return;
    }

    const int r0w = arow0 + warp_m * 32 + (lane >> 2);
    const int c0w = brow0 + warp_n * 64 + (lane & 3) * 2;
#pragma unroll
    for (int mi = 0; mi < 2; mi++) {
#pragma unroll
        for (int nf = 0; nf < 8; nf++) {
            int n = c0w + nf * 8;
            int m0 = r0w + mi * 16;
            int m1 = m0 + 8;
            float v0 = acc[mi][nf][0], v1 = acc[mi][nf][1];
            float v2 = acc[mi][nf][2], v3 = acc[mi][nf][3];
            if (EPI == 2) {
                float g0 = gate[m0 * H_ + (n >> 7)];
                float g1 = gate[m1 * H_ + (n >> 7)];
                const float* ve0 = ve + (size_t)m0 * C_ + n;
                const float* ve1 = ve + (size_t)m1 * C_ + n;
                v0 += g0 * ve0[0]; v1 += g0 * ve0[1];
                v2 += g1 * ve1[0]; v3 += g1 * ve1[1];
                int hh = n >> 7, dd = n & 127;
                size_t o0 = ((size_t)((m0 >> 11) * H_ + hh) * T_ + (m0 & 2047)) * D_ + dd;
                size_t o1 = ((size_t)((m1 >> 11) * H_ + hh) * T_ + (m1 & 2047)) * D_ + dd;
                store_hl(Oh + o0, Ol + o0, v0, v1);
                store_hl(Oh + o1, Ol + o1, v2, v3);
            } else {
                *(float2*)(Cout + (size_t)m0 * C_ + n) = make_float2(v0, v1);
                *(float2*)(Cout + (size_t)m1 * C_ + n) = make_float2(v2, v3);
            }
        }
    }
}

// ---------------- tensor-core flash attention (bf16 hi/lo split) -------------
#define TILE_B 17408                 // 64 rows * 272 B
#define KV_OFF (2*TILE_B)
#define STG (4*TILE_B)
#define ATT_SMEM (2*TILE_B + 2*STG)  // 174080

__global__ __launch_bounds__(128, 1) void attn_mma(
    const __nv_bfloat16* __restrict__ qh, const __nv_bfloat16* __restrict__ ql,
    const __nv_bfloat16* __restrict__ kh, const __nv_bfloat16* __restrict__ kl,
    const __nv_bfloat16* __restrict__ vh, const __nv_bfloat16* __restrict__ vl,
    __nv_bfloat16* __restrict__ yh, __nv_bfloat16* __restrict__ yl,
    const int* __restrict__ winp) {
    extern __shared__ char smc[];
    const uint32_t sb = smem_u32(smc);
    const int tid = threadIdx.x, w = tid >> 5, l = tid & 31;
    const int t0 = blockIdx.x * 64, h = blockIdx.y, b = blockIdx.z;
    int win = *winp;
    if (win <= 0 || win >= T_) win = T_;
    const size_t hb = (size_t)(b * H_ + h) * ((size_t)T_ * D_);

#pragma unroll
    for (int j = 0; j < 8; j++) {
        int u = tid + j * 128;
        int r = u >> 4, c = u & 15;
        uint32_t so = (uint32_t)(r * 272 + c * 16);
        size_t go = hb + (size_t)(t0 + r) * D_ + c * 8;
        cpasync16(sb + so, qh + go);
        cpasync16(sb + TILE_B + so, ql + go);
    }
    asm volatile("cp.async.commit_group;" ::: "memory");

    int start = t0 - win;
    if (start < 0) start = 0;
    start &= ~63;
    const int ntile = ((t0 - start) >> 6) + 1;

    auto loadKV = [&](int stg, int k0) {
        uint32_t bs = sb + KV_OFF + stg * STG;
#pragma unroll
        for (int j = 0; j < 8; j++) {
            int u = tid + j * 128;
            int r = u >> 4, c = u & 15;
            uint32_t so = (uint32_t)(r * 272 + c * 16);
            size_t go = hb + (size_t)(k0 + r) * D_ + c * 8;
            cpasync16(bs + so, kh + go);
            cpasync16(bs + TILE_B + so, kl + go);
            cpasync16(bs + 2 * TILE_B + so, vh + go);
            cpasync16(bs + 3 * TILE_B + so, vl + go);
        }
        asm volatile("cp.async.commit_group;" ::: "memory");
    };
    loadKV(0, start);
    if (ntile > 1) loadKV(1, start + 64);

    float o[16][4];
#pragma unroll
    for (int f = 0; f < 16; f++)
#pragma unroll
        for (int q = 0; q < 4; q++) o[f][q] = 0.f;
    float rm0 = -1e4f, rm1 = -1e4f, rl0 = 0.f, rl1 = 0.f;
    const float SC2 = 0.1275187989f;   // 1/sqrt(128) * log2(e)

    const uint32_t aoff = (uint32_t)((w * 16 + (l & 15)) * 272 + (l >> 4) * 16);
    const uint32_t boff = (uint32_t)((l & 15) * 272 + (l >> 4) * 16);
    const int r0 = t0 + w * 16 + (l >> 2), r1 = r0 + 8;

    for (int i = 0; i < ntile; i++) {
        int k0 = start + i * 64;
        if (i + 1 < ntile) asm volatile("cp.async.wait_group 1;" ::: "memory");
        else               asm volatile("cp.async.wait_group 0;" ::: "memory");
        __syncthreads();
        uint32_t bs = sb + KV_OFF + (i & 1) * STG;

        // ---- S = Qh*Kh + Qh*Kl + Ql*Kh  (product-major) ----
        float s[8][4];
#pragma unroll
        for (int f = 0; f < 8; f++)
#pragma unroll
            for (int q = 0; q < 4; q++) s[f][q] = 0.f;
#pragma unroll
        for (int ks = 0; ks < 8; ks++) {
            uint32_t aq[4], al4[4];
            uint32_t tk[4][4], uk[4][4];
            ldsm4(sb + aoff + ks * 32, aq);
            ldsm4(sb + TILE_B + aoff + ks * 32, al4);
#pragma unroll
            for (int ng = 0; ng < 4; ng++) {
                ldsm4(bs + boff + ng * 16 * 272 + ks * 32, tk[ng]);
                ldsm4(bs + TILE_B + boff + ng * 16 * 272 + ks * 32, uk[ng]);
            }
#pragma unroll
            for (int ng = 0; ng < 4; ng++) {
                MMA_BF16(s[ng * 2], aq, tk[ng][0], tk[ng][2]);
                MMA_BF16(s[ng * 2 + 1], aq, tk[ng][1], tk[ng][3]);
            }
#pragma unroll
            for (int ng = 0; ng < 4; ng++) {
                MMA_BF16(s[ng * 2], aq, uk[ng][0], uk[ng][2]);
                MMA_BF16(s[ng * 2 + 1], aq, uk[ng][1], uk[ng][3]);
            }
#pragma unroll
            for (int ng = 0; ng < 4; ng++) {
                MMA_BF16(s[ng * 2], al4, tk[ng][0], tk[ng][2]);
                MMA_BF16(s[ng * 2 + 1], al4, tk[ng][1], tk[ng][3]);
            }
        }

        // ---- masked online softmax (exp2 domain) ----
        float mx0 = -1e30f, mx1 = -1e30f;
#pragma unroll
        for (int nf = 0; nf < 8; nf++) {
            int c0 = k0 + nf * 8 + (l & 3) * 2, c1 = c0 + 1;
            float x0 = (c0 <= r0 && r0 - c0 <= win) ? s[nf][0] * SC2 : -1e30f;
            float x1 = (c1 <= r0 && r0 - c1 <= win) ? s[nf][1] * SC2 : -1e30f;
            float x2 = (c0 <= r1 && r1 - c0 <= win) ? s[nf][2] * SC2 : -1e30f;
            float x3 = (c1 <= r1 && r1 - c1 <= win) ? s[nf][3] * SC2 : -1e30f;
            s[nf][0] = x0; s[nf][1] = x1; s[nf][2] = x2; s[nf][3] = x3;
            mx0 = fmaxf(mx0, fmaxf(x0, x1));
            mx1 = fmaxf(mx1, fmaxf(x2, x3));
        }
        mx0 = fmaxf(mx0, __shfl_xor_sync(0xffffffffu, mx0, 1));
        mx0 = fmaxf(mx0, __shfl_xor_sync(0xffffffffu, mx0, 2));
        mx1 = fmaxf(mx1, __shfl_xor_sync(0xffffffffu, mx1, 1));
        mx1 = fmaxf(mx1, __shfl_xor_sync(0xffffffffu, mx1, 2));
        float mn0 = fmaxf(rm0, fmaxf(mx0, -1e4f));
        float mn1 = fmaxf(rm1, fmaxf(mx1, -1e4f));
        float corr0 = ex2f(rm0 - mn0), corr1 = ex2f(rm1 - mn1);
        float ls0 = 0.f, ls1 = 0.f;
#pragma unroll
        for (int nf = 0; nf < 8; nf++) {
            float p0 = ex2f(s[nf][0] - mn0);
            float p1 = ex2f(s[nf][1] - mn0);
            float p2 = ex2f(s[nf][2] - mn1);
            float p3 = ex2f(s[nf][3] - mn1);
            s[nf][0] = p0; s[nf][1] = p1; s[nf][2] = p2; s[nf][3] = p3;
            ls0 += p0 + p1; ls1 += p2 + p3;
        }
        ls0 += __shfl_xor_sync(0xffffffffu, ls0, 1);
        ls0 += __shfl_xor_sync(0xffffffffu, ls0, 2);
        ls1 += __shfl_xor_sync(0xffffffffu, ls1, 1);
        ls1 += __shfl_xor_sync(0xffffffffu, ls1, 2);
        rl0 = rl0 * corr0 + ls0;
        rl1 = rl1 * corr1 + ls1;
        rm0 = mn0; rm1 = mn1;
#pragma unroll
        for (int f = 0; f < 16; f++) {
            o[f][0] *= corr0; o[f][1] *= corr0;
            o[f][2] *= corr1; o[f][3] *= corr1;
        }

        // ---- O += Ph*Vh + Ph*Vl + Pl*Vh (product-major per ks) ----
#pragma unroll
        for (int ks = 0; ks < 4; ks++) {
            uint32_t ph[4], pl4[4];
            packhl(s[2 * ks][0], s[2 * ks][1], ph[0], pl4[0]);
            packhl(s[2 * ks][2], s[2 * ks][3], ph[1], pl4[1]);
            packhl(s[2 * ks + 1][0], s[2 * ks + 1][1], ph[2], pl4[2]);
            packhl(s[2 * ks + 1][2], s[2 * ks + 1][3], ph[3], pl4[3]);
            uint32_t voff = (uint32_t)((ks * 16 + (l & 15)) * 272 + (l >> 4) * 16);
            uint32_t tv[8][4], uv[8][4];
#pragma unroll
            for (int dg = 0; dg < 8; dg++) {
                ldsm4t(bs + 2 * TILE_B + voff + dg * 32, tv[dg]);
                ldsm4t(bs + 3 * TILE_B + voff + dg * 32, uv[dg]);
            }
#pragma unroll
            for (int dg = 0; dg < 8; dg++) {
                MMA_BF16(o[dg * 2], ph, tv[dg][0], tv[dg][1]);
                MMA_BF16(o[dg * 2 + 1], ph, tv[dg][2], tv[dg][3]);
            }
#pragma unroll
            for (int dg = 0; dg < 8; dg++) {
                MMA_BF16(o[dg * 2], ph, uv[dg][0], uv[dg][1]);
                MMA_BF16(o[dg * 2 + 1], ph, uv[dg][2], uv[dg][3]);
            }
#pragma unroll
            for (int dg = 0; dg < 8; dg++) {
                MMA_BF16(o[dg * 2], pl4, tv[dg][0], tv[dg][1]);
                MMA_BF16(o[dg * 2 + 1], pl4, tv[dg][2], tv[dg][3]);
            }
        }
        __syncthreads();
        if (i + 2 < ntile) loadKV(i & 1, k0 + 128);
    }

    float i0 = 1.f / rl0, i1 = 1.f / rl1;
    int m0r = t0 + w * 16 + (l >> 2);
#pragma unroll
    for (int f = 0; f < 16; f++) {
        int col = h * 128 + (f >> 1) * 16 + (f & 1) * 8 + (l & 3) * 2;
        size_t a0 = ((size_t)(b * T_ + m0r)) * C_ + col;
        size_t a1 = a0 + (size_t)8 * C_;
        store_hl(yh + a0, yl + a0, o[f][0] * i0, o[f][1] * i0);
        store_hl(yh + a1, yl + a1, o[f][2] * i1, o[f][3] * i1);
    }
}

// ---------------- launch ------------------------------------------------------
extern "C" void kernel_launch(void* const* d_in, const int* in_sizes, int n_in,
                              void* d_out, int out_size) {
    const float* x     = (const float*)d_in[0];
    const float* ve    = (const float*)d_in[1];
    const float* Wq    = (const float*)d_in[2];
    const float* Wk    = (const float*)d_in[3];
    const float* Wv    = (const float*)d_in[4];
    const float* Wproj = (const float*)d_in[5];
    const float* Wg    = (const float*)d_in[6];
    const float* cosp  = (const float*)d_in[7];
    const float* sinp  = (const float*)d_in[8];
    const int*   winp  = (const int*)d_in[9];
    float* out = (float*)d_out;

    void *pg, *pxh, *pxl, *pyh, *pyl;
    void *pqh, *pql, *pkh, *pkl, *pvh, *pvl;
    void *pwqh, *pwql, *pwkh, *pwkl, *pwvh, *pwvl, *pwph, *pwpl;
    cudaGetSymbolAddress(&pg,  g_gate);
    cudaGetSymbolAddress(&pxh, g_xh);  cudaGetSymbolAddress(&pxl, g_xl);
    cudaGetSymbolAddress(&pyh, g_yh);  cudaGetSymbolAddress(&pyl, g_yl);
    cudaGetSymbolAddress(&pqh, g_qh);  cudaGetSymbolAddress(&pql, g_ql);
    cudaGetSymbolAddress(&pkh, g_kh);  cudaGetSymbolAddress(&pkl, g_kl);
    cudaGetSymbolAddress(&pvh, g_vh);  cudaGetSymbolAddress(&pvl, g_vl);
    cudaGetSymbolAddress(&pwqh, g_wqh); cudaGetSymbolAddress(&pwql, g_wql);
    cudaGetSymbolAddress(&pwkh, g_wkh); cudaGetSymbolAddress(&pwkl, g_wkl);
    cudaGetSymbolAddress(&pwvh, g_wvh); cudaGetSymbolAddress(&pwvl, g_wvl);
    cudaGetSymbolAddress(&pwph, g_wph); cudaGetSymbolAddress(&pwpl, g_wpl);

    cudaFuncSetAttribute(gemm_mma<0>, cudaFuncAttributeMaxDynamicSharedMemorySize, GEMM_SMEM);
    cudaFuncSetAttribute(gemm_mma<1>, cudaFuncAttributeMaxDynamicSharedMemorySize, GEMM_SMEM);
    cudaFuncSetAttribute(gemm_mma<2>, cudaFuncAttributeMaxDynamicSharedMemorySize, GEMM_SMEM);
    cudaFuncSetAttribute(attn_mma, cudaFuncAttributeMaxDynamicSharedMemorySize, ATT_SMEM);

    // 0) splits
    split_kernel<<<M_*C_/1024, 256>>>(x, (__nv_bfloat16*)pxh, (__nv_bfloat16*)pxl, M_*C_);
    wsplit_kernel<<<dim3(C_*C_/1024, 4), 256>>>(
        Wq, Wk, Wv, Wproj,
        (__nv_bfloat16*)pwqh, (__nv_bfloat16*)pwql,
        (__nv_bfloat16*)pwkh, (__nv_bfloat16*)pwkl,
        (__nv_bfloat16*)pwvh, (__nv_bfloat16*)pwvl,
        (__nv_bfloat16*)pwph, (__nv_bfloat16*)pwpl);

    // 1) gate
    gate_kernel<<<(M_ * H_ + 255) / 256, 256>>>(x, Wg, (float*)pg);

    // 2) q, k projections (fused rope+rms+split), v projection (fused gate+split)
    dim3 ggrid(C_ / 128, M_ / 128);
    gemm_mma<1><<<ggrid, 256, GEMM_SMEM>>>((const __nv_bfloat16*)pxh, (const __nv_bfloat16*)pxl,
                                           (const __nv_bfloat16*)pwqh, (const __nv_bfloat16*)pwql,
                                           nullptr, (__nv_bfloat16*)pqh, (__nv_bfloat16*)pql,
                                           nullptr, nullptr, cosp, sinp);
    gemm_mma<1><<<ggrid, 256, GEMM_SMEM>>>((const __nv_bfloat16*)pxh, (const __nv_bfloat16*)pxl,
                                           (const __nv_bfloat16*)pwkh, (const __nv_bfloat16*)pwkl,
                                           nullptr, (__nv_bfloat16*)pkh, (__nv_bfloat16*)pkl,
                                           nullptr, nullptr, cosp, sinp);
    gemm_mma<2><<<ggrid, 256, GEMM_SMEM>>>((const __nv_bfloat16*)pxh, (const __nv_bfloat16*)pxl,
                                           (const __nv_bfloat16*)pwvh, (const __nv_bfloat16*)pwvl,
                                           nullptr, (__nv_bfloat16*)pvh, (__nv_bfloat16*)pvl,
                                           ve, (const float*)pg, nullptr, nullptr);

    // 3) tensor-core attention -> bf16 hi/lo y
    attn_mma<<<dim3(T_ / 64, H_, B_), 128, ATT_SMEM>>>(
        (const __nv_bfloat16*)pqh, (const __nv_bfloat16*)pql,
        (const __nv_bfloat16*)pkh, (const __nv_bfloat16*)pkl,
        (const __nv_bfloat16*)pvh, (const __nv_bfloat16*)pvl,
        (__nv_bfloat16*)pyh, (__nv_bfloat16*)pyl, winp);

    // 4) output projection
    gemm_mma<0><<<ggrid, 256, GEMM_SMEM>>>((const __nv_bfloat16*)pyh, (const __nv_bfloat16*)pyl,
                                           (const __nv_bfloat16*)pwph, (const __nv_bfloat16*)pwpl,
                                           out, nullptr, nullptr, nullptr, nullptr,
                                           nullptr, nullptr);
}